// round 1
// baseline (speedup 1.0000x reference)
#include <cuda_runtime.h>
#include <math.h>

#define B_   8
#define T_   4096
#define C_   384
#define H_   6
#define F_   64
#define E_   131072
#define DFF_ 1536
#define NEDGE (E_ + T_)
#define NEG_SLOPE 0.2f
#define LN_EPS 1e-5f

// ---------------- scratch (static device allocations; no cudaMalloc) --------
__device__ float g_xn[B_ * T_ * C_];       // LN output / reused
__device__ float g_h[B_ * T_ * C_];        // GAT features h = xn @ W_gat
__device__ float g_x1[B_ * T_ * C_];       // residual after GAT
__device__ float g_act[B_ * T_ * DFF_];    // FFN activations (201 MB)
__device__ float g_asrc[B_ * T_ * H_];
__device__ float g_adst[B_ * T_ * H_];
__device__ int   g_cnt[T_];
__device__ int   g_rowptr[T_ + 1];
__device__ int   g_fill[T_];
__device__ int   g_col[NEDGE];

// ---------------- CSR build --------------------------------------------------
__global__ void csr_init_kernel() {
    int t = blockIdx.x * blockDim.x + threadIdx.x;
    if (t < T_) g_cnt[t] = 1;   // self loop
}

__global__ void csr_count_kernel(const int* __restrict__ ei) {
    int e = blockIdx.x * blockDim.x + threadIdx.x;
    if (e < E_) atomicAdd(&g_cnt[ei[E_ + e]], 1);   // dst = ei[1][e]
}

__global__ void csr_scan_kernel() {
    // 1024 threads, 4 elements each, exclusive scan of g_cnt -> g_rowptr/g_fill
    int tid = threadIdx.x;
    int base = tid * 4;
    int c[4];
    int s = 0;
#pragma unroll
    for (int j = 0; j < 4; j++) { c[j] = g_cnt[base + j]; s += c[j]; }
    int lane = tid & 31, wid = tid >> 5;
    int v = s;
#pragma unroll
    for (int o = 1; o < 32; o <<= 1) {
        int n = __shfl_up_sync(0xffffffffu, v, o);
        if (lane >= o) v += n;
    }
    __shared__ int ws[32];
    if (lane == 31) ws[wid] = v;
    __syncthreads();
    if (wid == 0) {
        int w = ws[lane];
#pragma unroll
        for (int o = 1; o < 32; o <<= 1) {
            int n = __shfl_up_sync(0xffffffffu, w, o);
            if (lane >= o) w += n;
        }
        ws[lane] = w;
    }
    __syncthreads();
    int excl = v - s + (wid ? ws[wid - 1] : 0);
    int p = excl;
#pragma unroll
    for (int j = 0; j < 4; j++) {
        g_rowptr[base + j] = p;
        g_fill[base + j] = p;
        p += c[j];
    }
    if (tid == 1023) g_rowptr[T_] = p;
}

__global__ void csr_scatter_kernel(const int* __restrict__ ei) {
    int e = blockIdx.x * blockDim.x + threadIdx.x;
    if (e < E_) {
        int d = ei[E_ + e];
        int pos = atomicAdd(&g_fill[d], 1);
        g_col[pos] = ei[e];          // src
    } else if (e < NEDGE) {
        int t = e - E_;
        int pos = atomicAdd(&g_fill[t], 1);
        g_col[pos] = t;              // self loop
    }
}

// ---------------- LayerNorm (row = one token, 128 threads) -------------------
__global__ void ln_kernel(const float* __restrict__ x,
                          const float* __restrict__ g,
                          const float* __restrict__ b,
                          float* __restrict__ out) {
    int row = blockIdx.x;
    const float* xr = x + (size_t)row * C_;
    float* orow = out + (size_t)row * C_;
    int tid = threadIdx.x;
    float v0 = xr[tid], v1 = xr[tid + 128], v2 = xr[tid + 256];
    float s = v0 + v1 + v2;
    float ss = v0 * v0 + v1 * v1 + v2 * v2;
    int lane = tid & 31, wid = tid >> 5;
#pragma unroll
    for (int o = 16; o; o >>= 1) {
        s += __shfl_down_sync(0xffffffffu, s, o);
        ss += __shfl_down_sync(0xffffffffu, ss, o);
    }
    __shared__ float sm_s[4], sm_ss[4];
    if (lane == 0) { sm_s[wid] = s; sm_ss[wid] = ss; }
    __syncthreads();
    float ts = sm_s[0] + sm_s[1] + sm_s[2] + sm_s[3];
    float tss = sm_ss[0] + sm_ss[1] + sm_ss[2] + sm_ss[3];
    float mu = ts * (1.0f / C_);
    float var = tss * (1.0f / C_) - mu * mu;
    float r = rsqrtf(var + LN_EPS);
    orow[tid]       = (v0 - mu) * r * g[tid]       + b[tid];
    orow[tid + 128] = (v1 - mu) * r * g[tid + 128] + b[tid + 128];
    orow[tid + 256] = (v2 - mu) * r * g[tid + 256] + b[tid + 256];
}

// ---------------- attention coefficients a_src/a_dst -------------------------
__global__ void attn_kernel(const float* __restrict__ att_src,
                            const float* __restrict__ att_dst) {
    int row = blockIdx.x;           // b*T + t
    int tid = threadIdx.x;          // 384
    float hv = g_h[(size_t)row * C_ + tid];
    float ps = hv * att_src[tid];
    float pd = hv * att_dst[tid];
    int lane = tid & 31, wid = tid >> 5;
#pragma unroll
    for (int o = 16; o; o >>= 1) {
        ps += __shfl_down_sync(0xffffffffu, ps, o);
        pd += __shfl_down_sync(0xffffffffu, pd, o);
    }
    __shared__ float sp[12], sd[12];
    if (lane == 0) { sp[wid] = ps; sd[wid] = pd; }
    __syncthreads();
    if (tid < H_) {
        g_asrc[(size_t)row * H_ + tid] = sp[2 * tid] + sp[2 * tid + 1];
        g_adst[(size_t)row * H_ + tid] = sd[2 * tid] + sd[2 * tid + 1];
    }
}

// ---------------- fused GAT gather (softmax + aggregate + residual) ----------
__global__ void gather_kernel(const float* __restrict__ x,
                              const float* __restrict__ b_gat,
                              float* __restrict__ out) {
    int t = blockIdx.x;
    int b = blockIdx.y;
    int tid = threadIdx.x;          // 384
    int g = tid >> 6;               // head
    int l = tid & 63;
    int start = g_rowptr[t], end = g_rowptr[t + 1];
    float adst = g_adst[((size_t)b * T_ + t) * H_ + g];

    // pass 1: max over incoming edges for this head
    float mx = -1e30f;
    for (int e = start + l; e < end; e += 64) {
        int s = g_col[e];
        float a = g_asrc[((size_t)b * T_ + s) * H_ + g] + adst;
        a = a >= 0.0f ? a : NEG_SLOPE * a;
        mx = fmaxf(mx, a);
    }
    __shared__ float red[384];
    red[tid] = mx;
    __syncthreads();
#pragma unroll
    for (int o = 32; o; o >>= 1) {
        if (l < o) red[tid] = fmaxf(red[tid], red[tid + o]);
        __syncthreads();
    }
    float m = red[g << 6];
    __syncthreads();

    // pass 2: numerator + denominator together
    float acc = 0.0f, den = 0.0f;
    const float* hb = g_h + (size_t)b * T_ * C_;
    const float* asb = g_asrc + (size_t)b * T_ * H_;
    for (int e = start; e < end; e++) {
        int s = g_col[e];
        float a = asb[s * H_ + g] + adst;
        a = a >= 0.0f ? a : NEG_SLOPE * a;
        float ex = __expf(a - m);
        den += ex;
        acc += ex * hb[(size_t)s * C_ + tid];
    }
    size_t o = ((size_t)b * T_ + t) * C_ + tid;
    out[o] = x[o] + acc / den + b_gat[tid];
}

// ---------------- SGEMM: C = A(MxK) @ B(KxN) (+bias)(+relu)(+res) ------------
// EPI: 0 = none, 1 = bias+relu, 2 = bias+residual
template <int EPI>
__global__ __launch_bounds__(256)
void sgemm_kernel(const float* __restrict__ A, const float* __restrict__ Bm,
                  const float* __restrict__ bias, const float* __restrict__ res,
                  float* __restrict__ Cm, int M, int N, int K) {
    const int BM = 128, BN = 128, BK = 8;
    __shared__ float As[BK][BM];
    __shared__ float Bs[BK][BN];
    int tid = threadIdx.x;
    int bx = blockIdx.x, by = blockIdx.y;

    int arow = tid >> 1;
    int acol = (tid & 1) * 4;
    int brow = tid >> 5;
    int bcol = (tid & 31) * 4;
    const float* Ap = A + (size_t)(by * BM + arow) * K + acol;
    const float* Bp = Bm + (size_t)brow * N + bx * BN + bcol;

    int tx = tid & 15, ty = tid >> 4;
    float acc[8][8] = {};

    for (int k0 = 0; k0 < K; k0 += BK) {
        float4 av = *(const float4*)(Ap);
        float4 bv = *(const float4*)(Bp);
        Ap += BK;
        Bp += (size_t)BK * N;
        As[acol + 0][arow] = av.x;
        As[acol + 1][arow] = av.y;
        As[acol + 2][arow] = av.z;
        As[acol + 3][arow] = av.w;
        *(float4*)&Bs[brow][bcol] = bv;
        __syncthreads();
#pragma unroll
        for (int k = 0; k < BK; k++) {
            float a[8], bb[8];
            *(float4*)(a)     = *(float4*)&As[k][ty * 8];
            *(float4*)(a + 4) = *(float4*)&As[k][ty * 8 + 4];
            *(float4*)(bb)     = *(float4*)&Bs[k][tx * 8];
            *(float4*)(bb + 4) = *(float4*)&Bs[k][tx * 8 + 4];
#pragma unroll
            for (int i = 0; i < 8; i++)
#pragma unroll
                for (int j = 0; j < 8; j++)
                    acc[i][j] = fmaf(a[i], bb[j], acc[i][j]);
        }
        __syncthreads();
    }

    int crow0 = by * BM + ty * 8;
    int ccol0 = bx * BN + tx * 8;
    float bsv[8];
    if (EPI >= 1) {
#pragma unroll
        for (int j = 0; j < 8; j++) bsv[j] = bias[ccol0 + j];
    }
#pragma unroll
    for (int i = 0; i < 8; i++) {
        size_t ro = (size_t)(crow0 + i) * N + ccol0;
        float* Cr = Cm + ro;
#pragma unroll
        for (int j = 0; j < 8; j++) {
            float v = acc[i][j];
            if (EPI >= 1) v += bsv[j];
            if (EPI == 1) v = fmaxf(v, 0.0f);
            if (EPI == 2) v += res[ro + j];
            Cr[j] = v;
        }
    }
}

// ---------------- launch -----------------------------------------------------
extern "C" void kernel_launch(void* const* d_in, const int* in_sizes, int n_in,
                              void* d_out, int out_size) {
    const float* x      = (const float*)d_in[0];
    const int*   ei     = (const int*)d_in[1];
    const float* W_gat  = (const float*)d_in[2];
    const float* att_s  = (const float*)d_in[3];
    const float* att_d  = (const float*)d_in[4];
    const float* b_gat  = (const float*)d_in[5];
    const float* ln1_g  = (const float*)d_in[6];
    const float* ln1_b  = (const float*)d_in[7];
    const float* ln2_g  = (const float*)d_in[8];
    const float* ln2_b  = (const float*)d_in[9];
    const float* W1     = (const float*)d_in[10];
    const float* b1     = (const float*)d_in[11];
    const float* W2     = (const float*)d_in[12];
    const float* b2     = (const float*)d_in[13];
    float* out = (float*)d_out;

    float *p_xn, *p_h, *p_x1, *p_act;
    cudaGetSymbolAddress((void**)&p_xn, g_xn);
    cudaGetSymbolAddress((void**)&p_h, g_h);
    cudaGetSymbolAddress((void**)&p_x1, g_x1);
    cudaGetSymbolAddress((void**)&p_act, g_act);

    const int M = B_ * T_;

    // CSR build (depends only on edge_index)
    csr_init_kernel<<<(T_ + 255) / 256, 256>>>();
    csr_count_kernel<<<(E_ + 255) / 256, 256>>>(ei);
    csr_scan_kernel<<<1, 1024>>>();
    csr_scatter_kernel<<<(NEDGE + 255) / 256, 256>>>(ei);

    // LN1
    ln_kernel<<<M, 128>>>(x, ln1_g, ln1_b, p_xn);

    // h = xn @ W_gat
    {
        dim3 grid(C_ / 128, M / 128);
        sgemm_kernel<0><<<grid, 256>>>(p_xn, W_gat, nullptr, nullptr, p_h, M, C_, C_);
    }

    // a_src / a_dst
    attn_kernel<<<M, 384>>>(att_s, att_d);

    // fused softmax-gather + residual: g_x1 = x + GAT(xn) + b_gat
    {
        dim3 grid(T_, B_);
        gather_kernel<<<grid, 384>>>(x, b_gat, p_x1);
    }

    // LN2
    ln_kernel<<<M, 128>>>(p_x1, ln2_g, ln2_b, p_xn);

    // FFN1: act = relu(xn @ W1 + b1)
    {
        dim3 grid(DFF_ / 128, M / 128);
        sgemm_kernel<1><<<grid, 256>>>(p_xn, W1, b1, nullptr, p_act, M, DFF_, C_);
    }

    // FFN2: out = x1 + act @ W2 + b2
    {
        dim3 grid(C_ / 128, M / 128);
        sgemm_kernel<2><<<grid, 256>>>(p_act, W2, b2, p_x1, out, M, C_, DFF_);
    }
}

// round 4
// speedup vs baseline: 1.6954x; 1.6954x over previous
#include <cuda_runtime.h>
#include <math.h>

#define B_   8
#define T_   4096
#define C_   384
#define H_   6
#define F_   64
#define E_   131072
#define DFF_ 1536
#define NEDGE (E_ + T_)
#define NEG_SLOPE 0.2f
#define LN_EPS 1e-5f

// ---------------- scratch (static device allocations; no cudaMalloc) --------
__device__ float g_xn[B_ * T_ * C_];
__device__ float g_h[B_ * T_ * C_];
__device__ float g_x1[B_ * T_ * C_];
__device__ float g_act[B_ * T_ * DFF_];
__device__ float g_asrc[B_ * T_ * H_];
__device__ float g_adst[B_ * T_ * H_];
__device__ int   g_cnt[T_];
__device__ int   g_rowptr[T_ + 1];
__device__ int   g_fill[T_];
__device__ int   g_col[NEDGE];

// ---------------- CSR build --------------------------------------------------
__global__ void csr_init_kernel() {
    int t = blockIdx.x * blockDim.x + threadIdx.x;
    if (t < T_) g_cnt[t] = 1;   // self loop
}

__global__ void csr_count_kernel(const int* __restrict__ ei) {
    int e = blockIdx.x * blockDim.x + threadIdx.x;
    if (e < E_) atomicAdd(&g_cnt[ei[E_ + e]], 1);
}

__global__ void csr_scan_kernel() {
    int tid = threadIdx.x;
    int base = tid * 4;
    int c[4];
    int s = 0;
#pragma unroll
    for (int j = 0; j < 4; j++) { c[j] = g_cnt[base + j]; s += c[j]; }
    int lane = tid & 31, wid = tid >> 5;
    int v = s;
#pragma unroll
    for (int o = 1; o < 32; o <<= 1) {
        int n = __shfl_up_sync(0xffffffffu, v, o);
        if (lane >= o) v += n;
    }
    __shared__ int ws[32];
    if (lane == 31) ws[wid] = v;
    __syncthreads();
    if (wid == 0) {
        int w = ws[lane];
#pragma unroll
        for (int o = 1; o < 32; o <<= 1) {
            int n = __shfl_up_sync(0xffffffffu, w, o);
            if (lane >= o) w += n;
        }
        ws[lane] = w;
    }
    __syncthreads();
    int excl = v - s + (wid ? ws[wid - 1] : 0);
    int p = excl;
#pragma unroll
    for (int j = 0; j < 4; j++) {
        g_rowptr[base + j] = p;
        g_fill[base + j] = p;
        p += c[j];
    }
    if (tid == 1023) g_rowptr[T_] = p;
}

__global__ void csr_scatter_kernel(const int* __restrict__ ei) {
    int e = blockIdx.x * blockDim.x + threadIdx.x;
    if (e < E_) {
        int d = ei[E_ + e];
        int pos = atomicAdd(&g_fill[d], 1);
        g_col[pos] = ei[e];
    } else if (e < NEDGE) {
        int t = e - E_;
        int pos = atomicAdd(&g_fill[t], 1);
        g_col[pos] = t;
    }
}

// ---------------- LayerNorm --------------------------------------------------
__global__ void ln_kernel(const float* __restrict__ x,
                          const float* __restrict__ g,
                          const float* __restrict__ b,
                          float* __restrict__ out) {
    int row = blockIdx.x;
    const float* xr = x + (size_t)row * C_;
    float* orow = out + (size_t)row * C_;
    int tid = threadIdx.x;
    float v0 = xr[tid], v1 = xr[tid + 128], v2 = xr[tid + 256];
    float s = v0 + v1 + v2;
    float ss = v0 * v0 + v1 * v1 + v2 * v2;
    int lane = tid & 31, wid = tid >> 5;
#pragma unroll
    for (int o = 16; o; o >>= 1) {
        s += __shfl_down_sync(0xffffffffu, s, o);
        ss += __shfl_down_sync(0xffffffffu, ss, o);
    }
    __shared__ float sm_s[4], sm_ss[4];
    if (lane == 0) { sm_s[wid] = s; sm_ss[wid] = ss; }
    __syncthreads();
    float ts = sm_s[0] + sm_s[1] + sm_s[2] + sm_s[3];
    float tss = sm_ss[0] + sm_ss[1] + sm_ss[2] + sm_ss[3];
    float mu = ts * (1.0f / C_);
    float var = tss * (1.0f / C_) - mu * mu;
    float r = rsqrtf(var + LN_EPS);
    orow[tid]       = (v0 - mu) * r * g[tid]       + b[tid];
    orow[tid + 128] = (v1 - mu) * r * g[tid + 128] + b[tid + 128];
    orow[tid + 256] = (v2 - mu) * r * g[tid + 256] + b[tid + 256];
}

// ---------------- attention coefficients -------------------------------------
__global__ void attn_kernel(const float* __restrict__ att_src,
                            const float* __restrict__ att_dst) {
    int row = blockIdx.x;
    int tid = threadIdx.x;
    float hv = g_h[(size_t)row * C_ + tid];
    float ps = hv * att_src[tid];
    float pd = hv * att_dst[tid];
    int lane = tid & 31, wid = tid >> 5;
#pragma unroll
    for (int o = 16; o; o >>= 1) {
        ps += __shfl_down_sync(0xffffffffu, ps, o);
        pd += __shfl_down_sync(0xffffffffu, pd, o);
    }
    __shared__ float sp[12], sd[12];
    if (lane == 0) { sp[wid] = ps; sd[wid] = pd; }
    __syncthreads();
    if (tid < H_) {
        g_asrc[(size_t)row * H_ + tid] = sp[2 * tid] + sp[2 * tid + 1];
        g_adst[(size_t)row * H_ + tid] = sd[2 * tid] + sd[2 * tid + 1];
    }
}

// ---------------- fused GAT gather -------------------------------------------
__global__ void gather_kernel(const float* __restrict__ x,
                              const float* __restrict__ b_gat,
                              float* __restrict__ out) {
    int t = blockIdx.x;
    int b = blockIdx.y;
    int tid = threadIdx.x;
    int g = tid >> 6;
    int l = tid & 63;
    int start = g_rowptr[t], end = g_rowptr[t + 1];
    float adst = g_adst[((size_t)b * T_ + t) * H_ + g];

    float mx = -1e30f;
    for (int e = start + l; e < end; e += 64) {
        int s = g_col[e];
        float a = g_asrc[((size_t)b * T_ + s) * H_ + g] + adst;
        a = a >= 0.0f ? a : NEG_SLOPE * a;
        mx = fmaxf(mx, a);
    }
    __shared__ float red[384];
    red[tid] = mx;
    __syncthreads();
#pragma unroll
    for (int o = 32; o; o >>= 1) {
        if (l < o) red[tid] = fmaxf(red[tid], red[tid + o]);
        __syncthreads();
    }
    float m = red[g << 6];
    __syncthreads();

    float acc = 0.0f, den = 0.0f;
    const float* hb = g_h + (size_t)b * T_ * C_;
    const float* asb = g_asrc + (size_t)b * T_ * H_;
    for (int e = start; e < end; e++) {
        int s = g_col[e];
        float a = asb[s * H_ + g] + adst;
        a = a >= 0.0f ? a : NEG_SLOPE * a;
        float ex = __expf(a - m);
        den += ex;
        acc += ex * hb[(size_t)s * C_ + tid];
    }
    size_t o = ((size_t)b * T_ + t) * C_ + tid;
    out[o] = x[o] + acc / den + b_gat[tid];
}

// ---------------- tf32 tensor-core GEMM --------------------------------------
// C(MxN) = A(MxK) @ B(KxN);  EPI: 0 none, 1 bias+relu, 2 bias+residual
__device__ __forceinline__ unsigned f2tf(float f) {
    unsigned u;
    asm("cvt.rna.tf32.f32 %0, %1;" : "=r"(u) : "f"(f));
    return u;
}

__device__ __forceinline__ void mma_tf32(float* c, const unsigned* a, const unsigned* b) {
    asm volatile(
        "mma.sync.aligned.m16n8k8.row.col.f32.tf32.tf32.f32 "
        "{%0,%1,%2,%3}, {%4,%5,%6,%7}, {%8,%9}, {%0,%1,%2,%3};\n"
        : "+f"(c[0]), "+f"(c[1]), "+f"(c[2]), "+f"(c[3])
        : "r"(a[0]), "r"(a[1]), "r"(a[2]), "r"(a[3]), "r"(b[0]), "r"(b[1]));
}

#define APAD 4   // A smem stride 20 floats: frag LDS conflict-free
#define BPAD 8   // B smem stride 136 floats: frag LDS conflict-free

template <int EPI>
__global__ __launch_bounds__(256, 1)
void gemm_tc_kernel(const float* __restrict__ A, const float* __restrict__ Bm,
                    const float* __restrict__ bias, const float* __restrict__ res,
                    float* __restrict__ Cm, int M, int N, int K) {
    __shared__ unsigned As[2][128][16 + APAD];
    __shared__ unsigned Bs[2][16][128 + BPAD];

    const int tid = threadIdx.x;
    const int bx = blockIdx.x, by = blockIdx.y;
    const int warpId = tid >> 5, lane = tid & 31;
    const int wm = warpId & 1;        // 0..1 -> 64-row half
    const int wn = warpId >> 1;       // 0..3 -> 32-col quarter
    const int gID = lane >> 2, tg = lane & 3;

    // global->smem mapping
    const int ar = tid >> 2;          // 0..63
    const int ac = (tid & 3) * 4;     // 0,4,8,12
    const float* Ap = A + (size_t)(by * 128 + ar) * K + ac;
    const int br = tid >> 5;          // 0..7
    const int bc = (tid & 31) * 4;    // 0..124
    const float* Bp = Bm + (size_t)br * N + bx * 128 + bc;

    float acc[4][4][4] = {};
    float4 av0, av1, bv0, bv1;

    const int kIters = K >> 4;

    // prologue: tile 0
    av0 = *(const float4*)(Ap);
    av1 = *(const float4*)(Ap + (size_t)64 * K);
    bv0 = *(const float4*)(Bp);
    bv1 = *(const float4*)(Bp + (size_t)8 * N);
    {
        uint4 u;
        u.x = f2tf(av0.x); u.y = f2tf(av0.y); u.z = f2tf(av0.z); u.w = f2tf(av0.w);
        *(uint4*)&As[0][ar][ac] = u;
        u.x = f2tf(av1.x); u.y = f2tf(av1.y); u.z = f2tf(av1.z); u.w = f2tf(av1.w);
        *(uint4*)&As[0][ar + 64][ac] = u;
        u.x = f2tf(bv0.x); u.y = f2tf(bv0.y); u.z = f2tf(bv0.z); u.w = f2tf(bv0.w);
        *(uint4*)&Bs[0][br][bc] = u;
        u.x = f2tf(bv1.x); u.y = f2tf(bv1.y); u.z = f2tf(bv1.z); u.w = f2tf(bv1.w);
        *(uint4*)&Bs[0][br + 8][bc] = u;
    }
    __syncthreads();

    for (int it = 0; it < kIters; it++) {
        const int cur = it & 1;
        if (it + 1 < kIters) {
            int k0 = (it + 1) << 4;
            av0 = *(const float4*)(Ap + k0);
            av1 = *(const float4*)(Ap + (size_t)64 * K + k0);
            bv0 = *(const float4*)(Bp + (size_t)k0 * N);
            bv1 = *(const float4*)(Bp + (size_t)(k0 + 8) * N);
        }

        // compute on smem[cur]
#pragma unroll
        for (int kk = 0; kk < 16; kk += 8) {
            unsigned afr[4][4], bfr[4][2];
#pragma unroll
            for (int mi = 0; mi < 4; mi++) {
                int m0 = wm * 64 + mi * 16;
                afr[mi][0] = As[cur][m0 + gID][kk + tg];
                afr[mi][1] = As[cur][m0 + gID + 8][kk + tg];
                afr[mi][2] = As[cur][m0 + gID][kk + tg + 4];
                afr[mi][3] = As[cur][m0 + gID + 8][kk + tg + 4];
            }
#pragma unroll
            for (int ni = 0; ni < 4; ni++) {
                int n0 = wn * 32 + ni * 8;
                bfr[ni][0] = Bs[cur][kk + tg][n0 + gID];
                bfr[ni][1] = Bs[cur][kk + tg + 4][n0 + gID];
            }
#pragma unroll
            for (int mi = 0; mi < 4; mi++)
#pragma unroll
                for (int ni = 0; ni < 4; ni++)
                    mma_tf32(acc[mi][ni], afr[mi], bfr[ni]);
        }

        if (it + 1 < kIters) {
            __syncthreads();
            const int nxt = (it + 1) & 1;
            uint4 u;
            u.x = f2tf(av0.x); u.y = f2tf(av0.y); u.z = f2tf(av0.z); u.w = f2tf(av0.w);
            *(uint4*)&As[nxt][ar][ac] = u;
            u.x = f2tf(av1.x); u.y = f2tf(av1.y); u.z = f2tf(av1.z); u.w = f2tf(av1.w);
            *(uint4*)&As[nxt][ar + 64][ac] = u;
            u.x = f2tf(bv0.x); u.y = f2tf(bv0.y); u.z = f2tf(bv0.z); u.w = f2tf(bv0.w);
            *(uint4*)&Bs[nxt][br][bc] = u;
            u.x = f2tf(bv1.x); u.y = f2tf(bv1.y); u.z = f2tf(bv1.z); u.w = f2tf(bv1.w);
            *(uint4*)&Bs[nxt][br + 8][bc] = u;
            __syncthreads();
        }
    }

    // epilogue
#pragma unroll
    for (int mi = 0; mi < 4; mi++) {
        int row0 = by * 128 + wm * 64 + mi * 16 + gID;
#pragma unroll
        for (int ni = 0; ni < 4; ni++) {
            int col = bx * 128 + wn * 32 + ni * 8 + 2 * tg;
            float b0 = 0.f, b1 = 0.f;
            if (EPI >= 1) { b0 = bias[col]; b1 = bias[col + 1]; }
            float v0 = acc[mi][ni][0] + b0;
            float v1 = acc[mi][ni][1] + b1;
            float v2 = acc[mi][ni][2] + b0;
            float v3 = acc[mi][ni][3] + b1;
            size_t o0 = (size_t)row0 * N + col;
            size_t o1 = (size_t)(row0 + 8) * N + col;
            if (EPI == 1) {
                v0 = fmaxf(v0, 0.f); v1 = fmaxf(v1, 0.f);
                v2 = fmaxf(v2, 0.f); v3 = fmaxf(v3, 0.f);
            }
            if (EPI == 2) {
                v0 += res[o0]; v1 += res[o0 + 1];
                v2 += res[o1]; v3 += res[o1 + 1];
            }
            Cm[o0] = v0; Cm[o0 + 1] = v1;
            Cm[o1] = v2; Cm[o1 + 1] = v3;
        }
    }
}

// ---------------- launch -----------------------------------------------------
extern "C" void kernel_launch(void* const* d_in, const int* in_sizes, int n_in,
                              void* d_out, int out_size) {
    const float* x      = (const float*)d_in[0];
    const int*   ei     = (const int*)d_in[1];
    const float* W_gat  = (const float*)d_in[2];
    const float* att_s  = (const float*)d_in[3];
    const float* att_d  = (const float*)d_in[4];
    const float* b_gat  = (const float*)d_in[5];
    const float* ln1_g  = (const float*)d_in[6];
    const float* ln1_b  = (const float*)d_in[7];
    const float* ln2_g  = (const float*)d_in[8];
    const float* ln2_b  = (const float*)d_in[9];
    const float* W1     = (const float*)d_in[10];
    const float* b1     = (const float*)d_in[11];
    const float* W2     = (const float*)d_in[12];
    const float* b2     = (const float*)d_in[13];
    float* out = (float*)d_out;

    float *p_xn, *p_h, *p_x1, *p_act;
    cudaGetSymbolAddress((void**)&p_xn, g_xn);
    cudaGetSymbolAddress((void**)&p_h, g_h);
    cudaGetSymbolAddress((void**)&p_x1, g_x1);
    cudaGetSymbolAddress((void**)&p_act, g_act);

    const int M = B_ * T_;

    csr_init_kernel<<<(T_ + 255) / 256, 256>>>();
    csr_count_kernel<<<(E_ + 255) / 256, 256>>>(ei);
    csr_scan_kernel<<<1, 1024>>>();
    csr_scatter_kernel<<<(NEDGE + 255) / 256, 256>>>(ei);

    ln_kernel<<<M, 128>>>(x, ln1_g, ln1_b, p_xn);

    // h = xn @ W_gat  (tf32 tensor cores)
    {
        dim3 grid(C_ / 128, M / 128);
        gemm_tc_kernel<0><<<grid, 256>>>(p_xn, W_gat, nullptr, nullptr, p_h, M, C_, C_);
    }

    attn_kernel<<<M, 384>>>(att_s, att_d);

    {
        dim3 grid(T_, B_);
        gather_kernel<<<grid, 384>>>(x, b_gat, p_x1);
    }

    ln_kernel<<<M, 128>>>(p_x1, ln2_g, ln2_b, p_xn);

    // FFN1: act = relu(xn @ W1 + b1)
    {
        dim3 grid(DFF_ / 128, M / 128);
        gemm_tc_kernel<1><<<grid, 256>>>(p_xn, W1, b1, nullptr, p_act, M, DFF_, C_);
    }

    // FFN2: out = x1 + act @ W2 + b2
    {
        dim3 grid(C_ / 128, M / 128);
        gemm_tc_kernel<2><<<grid, 256>>>(p_act, W2, b2, p_x1, out, M, C_, DFF_);
    }
}

// round 7
// speedup vs baseline: 2.5738x; 1.5181x over previous
#include <cuda_runtime.h>
#include <math.h>

#define B_   8
#define T_   4096
#define C_   384
#define H_   6
#define F_   64
#define E_   131072
#define DFF_ 1536
#define NEDGE (E_ + T_)
#define NEG_SLOPE 0.2f
#define LN_EPS 1e-5f

// ---------------- scratch (static device allocations; no cudaMalloc) --------
__device__ float g_xn[B_ * T_ * C_];
__device__ float g_h[B_ * T_ * C_];
__device__ float g_x1[B_ * T_ * C_];
__device__ float g_act[B_ * T_ * DFF_];
__device__ float g_asrc[B_ * T_ * H_];
__device__ float g_adst[B_ * T_ * H_];
__device__ int   g_cnt[T_];
__device__ int   g_rowptr[T_ + 1];
__device__ int   g_fill[T_];
__device__ int   g_col[NEDGE];

// ---------------- CSR build --------------------------------------------------
__global__ void csr_init_kernel() {
    int t = blockIdx.x * blockDim.x + threadIdx.x;
    if (t < T_) g_cnt[t] = 1;   // self loop
}

__global__ void csr_count_kernel(const int* __restrict__ ei) {
    int e = blockIdx.x * blockDim.x + threadIdx.x;
    if (e < E_) atomicAdd(&g_cnt[ei[E_ + e]], 1);
}

__global__ void csr_scan_kernel() {
    int tid = threadIdx.x;
    int base = tid * 4;
    int c[4];
    int s = 0;
#pragma unroll
    for (int j = 0; j < 4; j++) { c[j] = g_cnt[base + j]; s += c[j]; }
    int lane = tid & 31, wid = tid >> 5;
    int v = s;
#pragma unroll
    for (int o = 1; o < 32; o <<= 1) {
        int n = __shfl_up_sync(0xffffffffu, v, o);
        if (lane >= o) v += n;
    }
    __shared__ int ws[32];
    if (lane == 31) ws[wid] = v;
    __syncthreads();
    if (wid == 0) {
        int w = ws[lane];
#pragma unroll
        for (int o = 1; o < 32; o <<= 1) {
            int n = __shfl_up_sync(0xffffffffu, w, o);
            if (lane >= o) w += n;
        }
        ws[lane] = w;
    }
    __syncthreads();
    int excl = v - s + (wid ? ws[wid - 1] : 0);
    int p = excl;
#pragma unroll
    for (int j = 0; j < 4; j++) {
        g_rowptr[base + j] = p;
        g_fill[base + j] = p;
        p += c[j];
    }
    if (tid == 1023) g_rowptr[T_] = p;
}

__global__ void csr_scatter_kernel(const int* __restrict__ ei) {
    int e = blockIdx.x * blockDim.x + threadIdx.x;
    if (e < E_) {
        int d = ei[E_ + e];
        int pos = atomicAdd(&g_fill[d], 1);
        g_col[pos] = ei[e];
    } else if (e < NEDGE) {
        int t = e - E_;
        int pos = atomicAdd(&g_fill[t], 1);
        g_col[pos] = t;
    }
}

// ---------------- LayerNorm --------------------------------------------------
__global__ void ln_kernel(const float* __restrict__ x,
                          const float* __restrict__ g,
                          const float* __restrict__ b,
                          float* __restrict__ out) {
    int row = blockIdx.x;
    const float* xr = x + (size_t)row * C_;
    float* orow = out + (size_t)row * C_;
    int tid = threadIdx.x;
    float v0 = xr[tid], v1 = xr[tid + 128], v2 = xr[tid + 256];
    float s = v0 + v1 + v2;
    float ss = v0 * v0 + v1 * v1 + v2 * v2;
    int lane = tid & 31, wid = tid >> 5;
#pragma unroll
    for (int o = 16; o; o >>= 1) {
        s += __shfl_down_sync(0xffffffffu, s, o);
        ss += __shfl_down_sync(0xffffffffu, ss, o);
    }
    __shared__ float sm_s[4], sm_ss[4];
    if (lane == 0) { sm_s[wid] = s; sm_ss[wid] = ss; }
    __syncthreads();
    float ts = sm_s[0] + sm_s[1] + sm_s[2] + sm_s[3];
    float tss = sm_ss[0] + sm_ss[1] + sm_ss[2] + sm_ss[3];
    float mu = ts * (1.0f / C_);
    float var = tss * (1.0f / C_) - mu * mu;
    float r = rsqrtf(var + LN_EPS);
    orow[tid]       = (v0 - mu) * r * g[tid]       + b[tid];
    orow[tid + 128] = (v1 - mu) * r * g[tid + 128] + b[tid + 128];
    orow[tid + 256] = (v2 - mu) * r * g[tid + 256] + b[tid + 256];
}

// ---------------- attention coefficients -------------------------------------
__global__ void attn_kernel(const float* __restrict__ att_src,
                            const float* __restrict__ att_dst) {
    int row = blockIdx.x;
    int tid = threadIdx.x;
    float hv = g_h[(size_t)row * C_ + tid];
    float ps = hv * att_src[tid];
    float pd = hv * att_dst[tid];
    int lane = tid & 31, wid = tid >> 5;
#pragma unroll
    for (int o = 16; o; o >>= 1) {
        ps += __shfl_down_sync(0xffffffffu, ps, o);
        pd += __shfl_down_sync(0xffffffffu, pd, o);
    }
    __shared__ float sp[12], sd[12];
    if (lane == 0) { sp[wid] = ps; sd[wid] = pd; }
    __syncthreads();
    if (tid < H_) {
        g_asrc[(size_t)row * H_ + tid] = sp[2 * tid] + sp[2 * tid + 1];
        g_adst[(size_t)row * H_ + tid] = sd[2 * tid] + sd[2 * tid + 1];
    }
}

// ---------------- fused GAT gather (cooperative edge weights) ----------------
__global__ void gather_kernel(const float* __restrict__ x,
                              const float* __restrict__ b_gat,
                              float* __restrict__ out) {
    int t = blockIdx.x;
    int b = blockIdx.y;
    int tid = threadIdx.x;          // 384
    int g = tid >> 6;               // head 0..5
    int l = tid & 63;
    int start = g_rowptr[t], end = g_rowptr[t + 1];
    const float* asb = g_asrc + (size_t)b * T_ * H_;
    float adst = g_adst[((size_t)b * T_ + t) * H_ + g];

    // pass 1: per-head max
    float mx = -1e30f;
    for (int e = start + l; e < end; e += 64) {
        int s = g_col[e];
        float a = asb[s * H_ + g] + adst;
        a = a >= 0.0f ? a : NEG_SLOPE * a;
        mx = fmaxf(mx, a);
    }
    __shared__ float red[384];
    red[tid] = mx;
    __syncthreads();
#pragma unroll
    for (int o = 32; o; o >>= 1) {
        if (l < o) red[tid] = fmaxf(red[tid], red[tid + o]);
        __syncthreads();
    }
    float m = red[g << 6];

    // pass 2: chunks of 64 edges; weights computed once per (edge, head)
    __shared__ float sw[H_][64];
    __shared__ int ssrc[64];
    float acc = 0.0f, den = 0.0f;
    const float* hb = g_h + (size_t)b * T_ * C_;

    for (int e0 = start; e0 < end; e0 += 64) {
        int n = min(64, end - e0);
        __syncthreads();            // protect prior chunk's smem reads
        if (l < n) {
            int s = g_col[e0 + l];
            if (g == 0) ssrc[l] = s;
            float a = asb[s * H_ + g] + adst;
            a = a >= 0.0f ? a : NEG_SLOPE * a;
            sw[g][l] = __expf(a - m);
        }
        __syncthreads();
#pragma unroll 4
        for (int j = 0; j < n; j++) {
            float w = sw[g][j];
            den += w;
            acc = fmaf(w, hb[(size_t)ssrc[j] * C_ + tid], acc);
        }
    }
    size_t o = ((size_t)b * T_ + t) * C_ + tid;
    out[o] = x[o] + acc / den + b_gat[tid];
}

// ---------------- tf32 tensor-core GEMM, cp.async double-buffered -------------
__device__ __forceinline__ void mma_tf32(float* c, const unsigned* a, const unsigned* b) {
    asm volatile(
        "mma.sync.aligned.m16n8k8.row.col.f32.tf32.tf32.f32 "
        "{%0,%1,%2,%3}, {%4,%5,%6,%7}, {%8,%9}, {%0,%1,%2,%3};\n"
        : "+f"(c[0]), "+f"(c[1]), "+f"(c[2]), "+f"(c[3])
        : "r"(a[0]), "r"(a[1]), "r"(a[2]), "r"(a[3]), "r"(b[0]), "r"(b[1]));
}

#define CP16(dst, src) \
    asm volatile("cp.async.cg.shared.global [%0], [%1], 16;\n" :: "r"(dst), "l"(src))
#define CP_COMMIT() asm volatile("cp.async.commit_group;\n")
#define CP_WAIT(N)  asm volatile("cp.async.wait_group %0;\n" :: "n"(N))

#define ASTRIDE 20   // padded A stride (floats): fragment LDS conflict-free
#define BSTRIDE 136  // padded B stride (floats): fragment LDS conflict-free

// EPI: 0 none, 1 bias+relu, 2 bias+residual
template <int EPI>
__global__ __launch_bounds__(256, 2)
void gemm_tc_kernel(const float* __restrict__ A, const float* __restrict__ Bm,
                    const float* __restrict__ bias, const float* __restrict__ res,
                    float* __restrict__ Cm, int M, int N, int K) {
    __shared__ float As[2][128][ASTRIDE];
    __shared__ float Bs[2][16][BSTRIDE];

    const int tid = threadIdx.x;
    const int bx = blockIdx.x, by = blockIdx.y;
    const int warpId = tid >> 5, lane = tid & 31;
    const int wm = warpId & 1;
    const int wn = warpId >> 1;
    const int gID = lane >> 2, tg = lane & 3;

    const int ar = tid >> 2;          // 0..63
    const int ac = (tid & 3) * 4;     // 0,4,8,12
    const float* Ap = A + (size_t)(by * 128 + ar) * K + ac;
    const int br = tid >> 5;          // 0..7
    const int bc = (tid & 31) * 4;    // 0..124
    const float* Bp = Bm + (size_t)br * N + bx * 128 + bc;

    unsigned sA0[2], sA1[2], sB0[2], sB1[2];
#pragma unroll
    for (int s = 0; s < 2; s++) {
        sA0[s] = (unsigned)__cvta_generic_to_shared(&As[s][ar][ac]);
        sA1[s] = (unsigned)__cvta_generic_to_shared(&As[s][ar + 64][ac]);
        sB0[s] = (unsigned)__cvta_generic_to_shared(&Bs[s][br][bc]);
        sB1[s] = (unsigned)__cvta_generic_to_shared(&Bs[s][br + 8][bc]);
    }

    float acc[4][4][4] = {};
    const int kIters = K >> 4;

    // prologue: stage 0
    {
        CP16(sA0[0], Ap);
        CP16(sA1[0], Ap + (size_t)64 * K);
        CP16(sB0[0], Bp);
        CP16(sB1[0], Bp + (size_t)8 * N);
        CP_COMMIT();
    }

    for (int it = 0; it < kIters; it++) {
        const int cur = it & 1;
        if (it + 1 < kIters) {
            const int nxt = (it + 1) & 1;
            int k0 = (it + 1) << 4;
            CP16(sA0[nxt], Ap + k0);
            CP16(sA1[nxt], Ap + (size_t)64 * K + k0);
            CP16(sB0[nxt], Bp + (size_t)k0 * N);
            CP16(sB1[nxt], Bp + (size_t)(k0 + 8) * N);
            CP_COMMIT();
            CP_WAIT(1);
        } else {
            CP_WAIT(0);
        }
        __syncthreads();

        const unsigned (*Asu)[ASTRIDE] =
            (const unsigned (*)[ASTRIDE])&As[cur][0][0];
        const unsigned (*Bsu)[BSTRIDE] =
            (const unsigned (*)[BSTRIDE])&Bs[cur][0][0];
#pragma unroll
        for (int kk = 0; kk < 16; kk += 8) {
            unsigned afr[4][4], bfr[4][2];
#pragma unroll
            for (int mi = 0; mi < 4; mi++) {
                int m0 = wm * 64 + mi * 16;
                afr[mi][0] = Asu[m0 + gID][kk + tg];
                afr[mi][1] = Asu[m0 + gID + 8][kk + tg];
                afr[mi][2] = Asu[m0 + gID][kk + tg + 4];
                afr[mi][3] = Asu[m0 + gID + 8][kk + tg + 4];
            }
#pragma unroll
            for (int ni = 0; ni < 4; ni++) {
                int n0 = wn * 32 + ni * 8;
                bfr[ni][0] = Bsu[kk + tg][n0 + gID];
                bfr[ni][1] = Bsu[kk + tg + 4][n0 + gID];
            }
#pragma unroll
            for (int mi = 0; mi < 4; mi++)
#pragma unroll
                for (int ni = 0; ni < 4; ni++)
                    mma_tf32(acc[mi][ni], afr[mi], bfr[ni]);
        }
        __syncthreads();
    }

    // epilogue
#pragma unroll
    for (int mi = 0; mi < 4; mi++) {
        int row0 = by * 128 + wm * 64 + mi * 16 + gID;
#pragma unroll
        for (int ni = 0; ni < 4; ni++) {
            int col = bx * 128 + wn * 32 + ni * 8 + 2 * tg;
            float b0 = 0.f, b1 = 0.f;
            if (EPI >= 1) { b0 = bias[col]; b1 = bias[col + 1]; }
            float v0 = acc[mi][ni][0] + b0;
            float v1 = acc[mi][ni][1] + b1;
            float v2 = acc[mi][ni][2] + b0;
            float v3 = acc[mi][ni][3] + b1;
            size_t o0 = (size_t)row0 * N + col;
            size_t o1 = (size_t)(row0 + 8) * N + col;
            if (EPI == 1) {
                v0 = fmaxf(v0, 0.f); v1 = fmaxf(v1, 0.f);
                v2 = fmaxf(v2, 0.f); v3 = fmaxf(v3, 0.f);
            }
            if (EPI == 2) {
                v0 += res[o0]; v1 += res[o0 + 1];
                v2 += res[o1]; v3 += res[o1 + 1];
            }
            Cm[o0] = v0; Cm[o0 + 1] = v1;
            Cm[o1] = v2; Cm[o1 + 1] = v3;
        }
    }
}

// ---------------- launch -----------------------------------------------------
extern "C" void kernel_launch(void* const* d_in, const int* in_sizes, int n_in,
                              void* d_out, int out_size) {
    const float* x      = (const float*)d_in[0];
    const int*   ei     = (const int*)d_in[1];
    const float* W_gat  = (const float*)d_in[2];
    const float* att_s  = (const float*)d_in[3];
    const float* att_d  = (const float*)d_in[4];
    const float* b_gat  = (const float*)d_in[5];
    const float* ln1_g  = (const float*)d_in[6];
    const float* ln1_b  = (const float*)d_in[7];
    const float* ln2_g  = (const float*)d_in[8];
    const float* ln2_b  = (const float*)d_in[9];
    const float* W1     = (const float*)d_in[10];
    const float* b1     = (const float*)d_in[11];
    const float* W2     = (const float*)d_in[12];
    const float* b2     = (const float*)d_in[13];
    float* out = (float*)d_out;

    float *p_xn, *p_h, *p_x1, *p_act;
    cudaGetSymbolAddress((void**)&p_xn, g_xn);
    cudaGetSymbolAddress((void**)&p_h, g_h);
    cudaGetSymbolAddress((void**)&p_x1, g_x1);
    cudaGetSymbolAddress((void**)&p_act, g_act);

    const int M = B_ * T_;

    csr_init_kernel<<<(T_ + 255) / 256, 256>>>();
    csr_count_kernel<<<(E_ + 255) / 256, 256>>>(ei);
    csr_scan_kernel<<<1, 1024>>>();
    csr_scatter_kernel<<<(NEDGE + 255) / 256, 256>>>(ei);

    ln_kernel<<<M, 128>>>(x, ln1_g, ln1_b, p_xn);

    // h = xn @ W_gat
    {
        dim3 grid(C_ / 128, M / 128);
        gemm_tc_kernel<0><<<grid, 256>>>(p_xn, W_gat, nullptr, nullptr, p_h, M, C_, C_);
    }

    attn_kernel<<<M, 384>>>(att_s, att_d);

    {
        dim3 grid(T_, B_);
        gather_kernel<<<grid, 384>>>(x, b_gat, p_x1);
    }

    ln_kernel<<<M, 128>>>(p_x1, ln2_g, ln2_b, p_xn);

    // FFN1: act = relu(xn @ W1 + b1)
    {
        dim3 grid(DFF_ / 128, M / 128);
        gemm_tc_kernel<1><<<grid, 256>>>(p_xn, W1, b1, nullptr, p_act, M, DFF_, C_);
    }

    // FFN2: out = x1 + act @ W2 + b2
    {
        dim3 grid(C_ / 128, M / 128);
        gemm_tc_kernel<2><<<grid, 256>>>(p_act, W2, b2, p_x1, out, M, C_, DFF_);
    }
}

// round 10
// speedup vs baseline: 3.6266x; 1.4090x over previous
#include <cuda_runtime.h>
#include <cuda_fp16.h>
#include <math.h>
#include <stdint.h>

#define B_   8
#define T_   4096
#define C_   384
#define H_   6
#define F_   64
#define E_   131072
#define DFF_ 1536
#define NEDGE (E_ + T_)
#define NEG_SLOPE 0.2f
#define LN_EPS 1e-5f

// ---------------- scratch ----------------------------------------------------
__device__ __half g_xnh[B_ * T_ * C_];     // LN output (half, GEMM A)
__device__ float  g_h[B_ * T_ * C_];       // GAT features (float, gather reads)
__device__ float  g_x1[B_ * T_ * C_];      // residual after GAT
__device__ __half g_acth[B_ * T_ * DFF_];  // FFN activations (half)
__device__ float  g_asrc[B_ * T_ * H_];
__device__ float  g_adst[B_ * T_ * H_];
__device__ int    g_cnt[T_];
__device__ int    g_rowptr[T_ + 1];
__device__ int    g_fill[T_];
__device__ int    g_col[NEDGE];
__device__ __half g_wgth[C_ * C_];         // W_gat^T [N][K] half
__device__ __half g_w1th[DFF_ * C_];       // W1^T
__device__ __half g_w2th[C_ * DFF_];       // W2^T

// ---------------- CSR build --------------------------------------------------
__global__ void csr_init_kernel() {
    int t = blockIdx.x * blockDim.x + threadIdx.x;
    if (t < T_) g_cnt[t] = 1;
}

__global__ void csr_count_kernel(const int* __restrict__ ei) {
    int e = blockIdx.x * blockDim.x + threadIdx.x;
    if (e < E_) atomicAdd(&g_cnt[ei[E_ + e]], 1);
}

__global__ void csr_scan_kernel() {
    int tid = threadIdx.x;
    int base = tid * 4;
    int c[4];
    int s = 0;
#pragma unroll
    for (int j = 0; j < 4; j++) { c[j] = g_cnt[base + j]; s += c[j]; }
    int lane = tid & 31, wid = tid >> 5;
    int v = s;
#pragma unroll
    for (int o = 1; o < 32; o <<= 1) {
        int n = __shfl_up_sync(0xffffffffu, v, o);
        if (lane >= o) v += n;
    }
    __shared__ int ws[32];
    if (lane == 31) ws[wid] = v;
    __syncthreads();
    if (wid == 0) {
        int w = ws[lane];
#pragma unroll
        for (int o = 1; o < 32; o <<= 1) {
            int n = __shfl_up_sync(0xffffffffu, w, o);
            if (lane >= o) w += n;
        }
        ws[lane] = w;
    }
    __syncthreads();
    int excl = v - s + (wid ? ws[wid - 1] : 0);
    int p = excl;
#pragma unroll
    for (int j = 0; j < 4; j++) {
        g_rowptr[base + j] = p;
        g_fill[base + j] = p;
        p += c[j];
    }
    if (tid == 1023) g_rowptr[T_] = p;
}

__global__ void csr_scatter_kernel(const int* __restrict__ ei) {
    int e = blockIdx.x * blockDim.x + threadIdx.x;
    if (e < E_) {
        int d = ei[E_ + e];
        int pos = atomicAdd(&g_fill[d], 1);
        g_col[pos] = ei[e];
    } else if (e < NEDGE) {
        int t = e - E_;
        int pos = atomicAdd(&g_fill[t], 1);
        g_col[pos] = t;
    }
}

// ---------------- weight transpose (float in -> half out, [R][C]->[C][R]) ----
__global__ void transpose_h_kernel(const float* __restrict__ in,
                                   __half* __restrict__ outp, int R, int Cc) {
    __shared__ float t[32][33];
    int x = blockIdx.x * 32 + threadIdx.x;
    int y = blockIdx.y * 32 + threadIdx.y;
#pragma unroll
    for (int j = 0; j < 32; j += 8)
        t[threadIdx.y + j][threadIdx.x] = in[(size_t)(y + j) * Cc + x];
    __syncthreads();
    x = blockIdx.y * 32 + threadIdx.x;
    y = blockIdx.x * 32 + threadIdx.y;
#pragma unroll
    for (int j = 0; j < 32; j += 8)
        outp[(size_t)(y + j) * R + x] = __float2half_rn(t[threadIdx.x][threadIdx.y + j]);
}

// ---------------- LayerNorm (half output) ------------------------------------
__global__ void ln_kernel(const float* __restrict__ x,
                          const float* __restrict__ g,
                          const float* __restrict__ b,
                          __half* __restrict__ out) {
    int row = blockIdx.x;
    const float* xr = x + (size_t)row * C_;
    __half* orow = out + (size_t)row * C_;
    int tid = threadIdx.x;
    float v0 = xr[tid], v1 = xr[tid + 128], v2 = xr[tid + 256];
    float s = v0 + v1 + v2;
    float ss = v0 * v0 + v1 * v1 + v2 * v2;
    int lane = tid & 31, wid = tid >> 5;
#pragma unroll
    for (int o = 16; o; o >>= 1) {
        s += __shfl_down_sync(0xffffffffu, s, o);
        ss += __shfl_down_sync(0xffffffffu, ss, o);
    }
    __shared__ float sm_s[4], sm_ss[4];
    if (lane == 0) { sm_s[wid] = s; sm_ss[wid] = ss; }
    __syncthreads();
    float ts = sm_s[0] + sm_s[1] + sm_s[2] + sm_s[3];
    float tss = sm_ss[0] + sm_ss[1] + sm_ss[2] + sm_ss[3];
    float mu = ts * (1.0f / C_);
    float var = tss * (1.0f / C_) - mu * mu;
    float r = rsqrtf(var + LN_EPS);
    orow[tid]       = __float2half_rn((v0 - mu) * r * g[tid]       + b[tid]);
    orow[tid + 128] = __float2half_rn((v1 - mu) * r * g[tid + 128] + b[tid + 128]);
    orow[tid + 256] = __float2half_rn((v2 - mu) * r * g[tid + 256] + b[tid + 256]);
}

// ---------------- attention coefficients -------------------------------------
__global__ void attn_kernel(const float* __restrict__ att_src,
                            const float* __restrict__ att_dst) {
    int row = blockIdx.x;
    int tid = threadIdx.x;
    float hv = g_h[(size_t)row * C_ + tid];
    float ps = hv * att_src[tid];
    float pd = hv * att_dst[tid];
    int lane = tid & 31, wid = tid >> 5;
#pragma unroll
    for (int o = 16; o; o >>= 1) {
        ps += __shfl_down_sync(0xffffffffu, ps, o);
        pd += __shfl_down_sync(0xffffffffu, pd, o);
    }
    __shared__ float sp[12], sd[12];
    if (lane == 0) { sp[wid] = ps; sd[wid] = pd; }
    __syncthreads();
    if (tid < H_) {
        g_asrc[(size_t)row * H_ + tid] = sp[2 * tid] + sp[2 * tid + 1];
        g_adst[(size_t)row * H_ + tid] = sd[2 * tid] + sd[2 * tid + 1];
    }
}

// ---------------- fused GAT gather -------------------------------------------
__global__ void gather_kernel(const float* __restrict__ x,
                              const float* __restrict__ b_gat,
                              float* __restrict__ out) {
    int t = blockIdx.x;
    int b = blockIdx.y;
    int tid = threadIdx.x;
    int g = tid >> 6;
    int l = tid & 63;
    int start = g_rowptr[t], end = g_rowptr[t + 1];
    const float* asb = g_asrc + (size_t)b * T_ * H_;
    float adst = g_adst[((size_t)b * T_ + t) * H_ + g];

    float mx = -1e30f;
    for (int e = start + l; e < end; e += 64) {
        int s = g_col[e];
        float a = asb[s * H_ + g] + adst;
        a = a >= 0.0f ? a : NEG_SLOPE * a;
        mx = fmaxf(mx, a);
    }
    __shared__ float red[384];
    red[tid] = mx;
    __syncthreads();
#pragma unroll
    for (int o = 32; o; o >>= 1) {
        if (l < o) red[tid] = fmaxf(red[tid], red[tid + o]);
        __syncthreads();
    }
    float m = red[g << 6];

    __shared__ float sw[H_][64];
    __shared__ int ssrc[64];
    float acc = 0.0f, den = 0.0f;
    const float* hb = g_h + (size_t)b * T_ * C_;

    for (int e0 = start; e0 < end; e0 += 64) {
        int n = min(64, end - e0);
        __syncthreads();
        if (l < n) {
            int s = g_col[e0 + l];
            if (g == 0) ssrc[l] = s;
            float a = asb[s * H_ + g] + adst;
            a = a >= 0.0f ? a : NEG_SLOPE * a;
            sw[g][l] = __expf(a - m);
        }
        __syncthreads();
#pragma unroll 4
        for (int j = 0; j < n; j++) {
            float w = sw[g][j];
            den += w;
            acc = fmaf(w, hb[(size_t)ssrc[j] * C_ + tid], acc);
        }
    }
    size_t o = ((size_t)b * T_ + t) * C_ + tid;
    out[o] = x[o] + acc / den + b_gat[tid];
}

// ================== fp16 mma.sync GEMM ======================================
__device__ __forceinline__ void mma_f16(float* c, const uint32_t* a, const uint32_t* b) {
    asm volatile(
        "mma.sync.aligned.m16n8k16.row.col.f32.f16.f16.f32 "
        "{%0,%1,%2,%3}, {%4,%5,%6,%7}, {%8,%9}, {%0,%1,%2,%3};\n"
        : "+f"(c[0]), "+f"(c[1]), "+f"(c[2]), "+f"(c[3])
        : "r"(a[0]), "r"(a[1]), "r"(a[2]), "r"(a[3]), "r"(b[0]), "r"(b[1]));
}

#define CP16(dst, src) \
    asm volatile("cp.async.cg.shared.global [%0], [%1], 16;\n" :: "r"(dst), "l"(src))
#define CP_COMMIT() asm volatile("cp.async.commit_group;\n")
#define CP_WAIT(N)  asm volatile("cp.async.wait_group %0;\n" :: "n"(N))

__device__ __forceinline__ uint32_t smem_u32(const void* p) {
    uint32_t a;
    asm("{ .reg .u64 t; cvta.to.shared.u64 t, %1; cvt.u32.u64 %0, t; }"
        : "=r"(a) : "l"(p));
    return a;
}

#define HSTRIDE 40   // half stride per row: word bank = row*20+tg -> conflict-free

// C(MxN) = A(MxK:half) @ Bt(NxK:half)^T ; EPI: 0 float out, 1 bias+relu half out,
// 2 bias+residual float out
template <int EPI>
__global__ __launch_bounds__(256, 2)
void gemm_f16_kernel(const __half* __restrict__ A, const __half* __restrict__ Bt,
                     const float* __restrict__ bias, const float* __restrict__ res,
                     void* __restrict__ Cout, int M, int N, int K) {
    __shared__ __align__(16) __half As[2][128][HSTRIDE];
    __shared__ __align__(16) __half Bs[2][128][HSTRIDE];

    const int tid = threadIdx.x;
    const int bx = blockIdx.x, by = blockIdx.y;
    const int warpId = tid >> 5, lane = tid & 31;
    const int wm = warpId & 1;        // 64-row half
    const int wn = warpId >> 1;       // 32-col quarter
    const int gID = lane >> 2, tg = lane & 3;

    const __half* Abase = A + (size_t)(by * 128) * K;
    const __half* Bbase = Bt + (size_t)(bx * 128) * K;

    const int nCh = K >> 5;           // 32 halves per chunk

    // fill chunk c into buffer b: 1024 x 16B segments (A 512 + B 512)
#define DO_FILL(c, b) do { \
        const __half* As_ = Abase + (c) * 32; \
        const __half* Bs_ = Bbase + (c) * 32; \
        uint32_t ab = smem_u32(&As[b][0][0]); \
        uint32_t bb = smem_u32(&Bs[b][0][0]); \
        _Pragma("unroll") \
        for (int u = 0; u < 4; u++) { \
            int o = tid + u * 256; \
            int o2 = o & 511; \
            int r_ = o2 >> 2, s_ = o2 & 3; \
            uint32_t doff = (uint32_t)(r_ * (HSTRIDE * 2) + s_ * 16); \
            if (o < 512) CP16(ab + doff, As_ + (size_t)r_ * K + s_ * 8); \
            else         CP16(bb + doff, Bs_ + (size_t)r_ * K + s_ * 8); \
        } \
        CP_COMMIT(); \
    } while (0)

    float acc[4][4][4] = {};

    DO_FILL(0, 0);

    for (int it = 0; it < nCh; it++) {
        const int cur = it & 1;
        if (it + 1 < nCh) {
            DO_FILL(it + 1, (it + 1) & 1);
            CP_WAIT(1);
        } else {
            CP_WAIT(0);
        }
        __syncthreads();

#pragma unroll
        for (int kk = 0; kk < 32; kk += 16) {
            uint32_t afr[4][4], bfr[4][2];
#pragma unroll
            for (int mi = 0; mi < 4; mi++) {
                int m0 = wm * 64 + mi * 16;
                afr[mi][0] = *(const uint32_t*)&As[cur][m0 + gID][kk + 2 * tg];
                afr[mi][1] = *(const uint32_t*)&As[cur][m0 + gID + 8][kk + 2 * tg];
                afr[mi][2] = *(const uint32_t*)&As[cur][m0 + gID][kk + 2 * tg + 8];
                afr[mi][3] = *(const uint32_t*)&As[cur][m0 + gID + 8][kk + 2 * tg + 8];
            }
#pragma unroll
            for (int ni = 0; ni < 4; ni++) {
                int n0 = wn * 32 + ni * 8;
                bfr[ni][0] = *(const uint32_t*)&Bs[cur][n0 + gID][kk + 2 * tg];
                bfr[ni][1] = *(const uint32_t*)&Bs[cur][n0 + gID][kk + 2 * tg + 8];
            }
#pragma unroll
            for (int mi = 0; mi < 4; mi++)
#pragma unroll
                for (int ni = 0; ni < 4; ni++)
                    mma_f16(acc[mi][ni], afr[mi], bfr[ni]);
        }
        __syncthreads();
    }

    // epilogue: c0,c1 = (row gID, cols 2tg,2tg+1); c2,c3 = row gID+8
#pragma unroll
    for (int mi = 0; mi < 4; mi++) {
        int row0 = by * 128 + wm * 64 + mi * 16 + gID;
#pragma unroll
        for (int ni = 0; ni < 4; ni++) {
            int col = bx * 128 + wn * 32 + ni * 8 + 2 * tg;
            float b0 = 0.f, b1 = 0.f;
            if (EPI >= 1) { b0 = bias[col]; b1 = bias[col + 1]; }
            float v0 = acc[mi][ni][0] + b0;
            float v1 = acc[mi][ni][1] + b1;
            float v2 = acc[mi][ni][2] + b0;
            float v3 = acc[mi][ni][3] + b1;
            size_t o0 = (size_t)row0 * N + col;
            size_t o1 = (size_t)(row0 + 8) * N + col;
            if (EPI == 1) {
                v0 = fmaxf(v0, 0.f); v1 = fmaxf(v1, 0.f);
                v2 = fmaxf(v2, 0.f); v3 = fmaxf(v3, 0.f);
                __half* Ch = (__half*)Cout;
                *(__half2*)(Ch + o0) = __floats2half2_rn(v0, v1);
                *(__half2*)(Ch + o1) = __floats2half2_rn(v2, v3);
            } else {
                float* Cf = (float*)Cout;
                if (EPI == 2) {
                    v0 += res[o0]; v1 += res[o0 + 1];
                    v2 += res[o1]; v3 += res[o1 + 1];
                }
                Cf[o0] = v0; Cf[o0 + 1] = v1;
                Cf[o1] = v2; Cf[o1 + 1] = v3;
            }
        }
    }
#undef DO_FILL
}

// ---------------- launch -----------------------------------------------------
extern "C" void kernel_launch(void* const* d_in, const int* in_sizes, int n_in,
                              void* d_out, int out_size) {
    const float* x      = (const float*)d_in[0];
    const int*   ei     = (const int*)d_in[1];
    const float* W_gat  = (const float*)d_in[2];
    const float* att_s  = (const float*)d_in[3];
    const float* att_d  = (const float*)d_in[4];
    const float* b_gat  = (const float*)d_in[5];
    const float* ln1_g  = (const float*)d_in[6];
    const float* ln1_b  = (const float*)d_in[7];
    const float* ln2_g  = (const float*)d_in[8];
    const float* ln2_b  = (const float*)d_in[9];
    const float* W1     = (const float*)d_in[10];
    const float* b1     = (const float*)d_in[11];
    const float* W2     = (const float*)d_in[12];
    const float* b2     = (const float*)d_in[13];
    float* out = (float*)d_out;

    float *p_h, *p_x1;
    __half *p_xnh, *p_acth, *p_wgth, *p_w1th, *p_w2th;
    cudaGetSymbolAddress((void**)&p_h, g_h);
    cudaGetSymbolAddress((void**)&p_x1, g_x1);
    cudaGetSymbolAddress((void**)&p_xnh, g_xnh);
    cudaGetSymbolAddress((void**)&p_acth, g_acth);
    cudaGetSymbolAddress((void**)&p_wgth, g_wgth);
    cudaGetSymbolAddress((void**)&p_w1th, g_w1th);
    cudaGetSymbolAddress((void**)&p_w2th, g_w2th);

    const int M = B_ * T_;

    // weight transposes -> half [N][K]
    {
        dim3 blk(32, 8);
        transpose_h_kernel<<<dim3(C_ / 32, C_ / 32), blk>>>(W_gat, p_wgth, C_, C_);
        transpose_h_kernel<<<dim3(DFF_ / 32, C_ / 32), blk>>>(W1, p_w1th, C_, DFF_);
        transpose_h_kernel<<<dim3(C_ / 32, DFF_ / 32), blk>>>(W2, p_w2th, DFF_, C_);
    }

    csr_init_kernel<<<(T_ + 255) / 256, 256>>>();
    csr_count_kernel<<<(E_ + 255) / 256, 256>>>(ei);
    csr_scan_kernel<<<1, 1024>>>();
    csr_scatter_kernel<<<(NEDGE + 255) / 256, 256>>>(ei);

    ln_kernel<<<M, 128>>>(x, ln1_g, ln1_b, p_xnh);

    // h = xn @ W_gat  (fp16 mma, float out)
    {
        dim3 grid(C_ / 128, M / 128);
        gemm_f16_kernel<0><<<grid, 256>>>(p_xnh, p_wgth, nullptr, nullptr,
                                          p_h, M, C_, C_);
    }

    attn_kernel<<<M, 384>>>(att_s, att_d);

    {
        dim3 grid(T_, B_);
        gather_kernel<<<grid, 384>>>(x, b_gat, p_x1);
    }

    ln_kernel<<<M, 128>>>(p_x1, ln2_g, ln2_b, p_xnh);

    // FFN1: act = relu(xn @ W1 + b1)  (half out)
    {
        dim3 grid(DFF_ / 128, M / 128);
        gemm_f16_kernel<1><<<grid, 256>>>(p_xnh, p_w1th, b1, nullptr,
                                          p_acth, M, DFF_, C_);
    }

    // FFN2: out = x1 + act @ W2 + b2  (float out)
    {
        dim3 grid(C_ / 128, M / 128);
        gemm_f16_kernel<2><<<grid, 256>>>(p_acth, p_w2th, b2, p_x1,
                                          out, M, C_, DFF_);
    }
}

// round 12
// speedup vs baseline: 4.5379x; 1.2513x over previous
#include <cuda_runtime.h>
#include <cuda_fp16.h>
#include <math.h>
#include <stdint.h>

#define B_   8
#define T_   4096
#define C_   384
#define H_   6
#define F_   64
#define E_   131072
#define DFF_ 1536
#define NEDGE (E_ + T_)
#define NEG_SLOPE 0.2f
#define LN_EPS 1e-5f

// ---------------- scratch ----------------------------------------------------
__device__ __half g_xnh[B_ * T_ * C_];     // LN output (half, GEMM A)
__device__ __half g_hh[B_ * T_ * C_];      // GAT features h (half)
__device__ float  g_x1[B_ * T_ * C_];      // residual after GAT
__device__ __half g_acth[B_ * T_ * DFF_];  // FFN activations (half)
__device__ float  g_asrc[B_ * T_ * H_];
__device__ float  g_adst[B_ * T_ * H_];
__device__ int    g_cnt[T_];
__device__ int    g_rowptr[T_ + 1];
__device__ int    g_fill[T_];
__device__ int    g_col[NEDGE];
__device__ __half g_wgth[C_ * C_];         // W_gat^T [N][K] half
__device__ __half g_w1th[DFF_ * C_];       // W1^T
__device__ __half g_w2th[C_ * DFF_];       // W2^T

// ---------------- CSR build --------------------------------------------------
// g_cnt starts at 0 (globals zero-init; csr_scan resets it each launch).
__global__ void csr_count_kernel(const int* __restrict__ ei) {
    int e = blockIdx.x * blockDim.x + threadIdx.x;
    if (e < E_) atomicAdd(&g_cnt[ei[E_ + e]], 1);
}

__global__ void csr_scan_kernel() {
    int tid = threadIdx.x;
    int base = tid * 4;
    int c[4];
    int s = 0;
#pragma unroll
    for (int j = 0; j < 4; j++) { c[j] = g_cnt[base + j] + 1; s += c[j]; } // +1 self loop
    int lane = tid & 31, wid = tid >> 5;
    int v = s;
#pragma unroll
    for (int o = 1; o < 32; o <<= 1) {
        int n = __shfl_up_sync(0xffffffffu, v, o);
        if (lane >= o) v += n;
    }
    __shared__ int ws[32];
    if (lane == 31) ws[wid] = v;
    __syncthreads();
    if (wid == 0) {
        int w = ws[lane];
#pragma unroll
        for (int o = 1; o < 32; o <<= 1) {
            int n = __shfl_up_sync(0xffffffffu, w, o);
            if (lane >= o) w += n;
        }
        ws[lane] = w;
    }
    __syncthreads();
    int excl = v - s + (wid ? ws[wid - 1] : 0);
    int p = excl;
#pragma unroll
    for (int j = 0; j < 4; j++) {
        g_rowptr[base + j] = p;
        g_fill[base + j] = p;
        g_cnt[base + j] = 0;          // reset for next launch (graph replay)
        p += c[j];
    }
    if (tid == 1023) g_rowptr[T_] = p;
}

__global__ void csr_scatter_kernel(const int* __restrict__ ei) {
    int e = blockIdx.x * blockDim.x + threadIdx.x;
    if (e < E_) {
        int d = ei[E_ + e];
        int pos = atomicAdd(&g_fill[d], 1);
        g_col[pos] = ei[e];
    } else if (e < NEDGE) {
        int t = e - E_;
        int pos = atomicAdd(&g_fill[t], 1);
        g_col[pos] = t;
    }
}

// ---------------- weight transpose (float in -> half out) --------------------
__global__ void transpose_h_kernel(const float* __restrict__ in,
                                   __half* __restrict__ outp, int R, int Cc) {
    __shared__ float t[32][33];
    int x = blockIdx.x * 32 + threadIdx.x;
    int y = blockIdx.y * 32 + threadIdx.y;
#pragma unroll
    for (int j = 0; j < 32; j += 8)
        t[threadIdx.y + j][threadIdx.x] = in[(size_t)(y + j) * Cc + x];
    __syncthreads();
    x = blockIdx.y * 32 + threadIdx.x;
    y = blockIdx.x * 32 + threadIdx.y;
#pragma unroll
    for (int j = 0; j < 32; j += 8)
        outp[(size_t)(y + j) * R + x] = __float2half_rn(t[threadIdx.x][threadIdx.y + j]);
}

// ---------------- LayerNorm (float in, half out) ------------------------------
__global__ void ln_kernel(const float* __restrict__ x,
                          const float* __restrict__ g,
                          const float* __restrict__ b,
                          __half* __restrict__ out) {
    int row = blockIdx.x;
    const float* xr = x + (size_t)row * C_;
    __half* orow = out + (size_t)row * C_;
    int tid = threadIdx.x;
    float v0 = xr[tid], v1 = xr[tid + 128], v2 = xr[tid + 256];
    float s = v0 + v1 + v2;
    float ss = v0 * v0 + v1 * v1 + v2 * v2;
    int lane = tid & 31, wid = tid >> 5;
#pragma unroll
    for (int o = 16; o; o >>= 1) {
        s += __shfl_down_sync(0xffffffffu, s, o);
        ss += __shfl_down_sync(0xffffffffu, ss, o);
    }
    __shared__ float sm_s[4], sm_ss[4];
    if (lane == 0) { sm_s[wid] = s; sm_ss[wid] = ss; }
    __syncthreads();
    float ts = sm_s[0] + sm_s[1] + sm_s[2] + sm_s[3];
    float tss = sm_ss[0] + sm_ss[1] + sm_ss[2] + sm_ss[3];
    float mu = ts * (1.0f / C_);
    float var = tss * (1.0f / C_) - mu * mu;
    float r = rsqrtf(var + LN_EPS);
    orow[tid]       = __float2half_rn((v0 - mu) * r * g[tid]       + b[tid]);
    orow[tid + 128] = __float2half_rn((v1 - mu) * r * g[tid + 128] + b[tid + 128]);
    orow[tid + 256] = __float2half_rn((v2 - mu) * r * g[tid + 256] + b[tid + 256]);
}

// ---------------- attention coefficients (192 thr, warp = head) --------------
__global__ void attn_kernel(const float* __restrict__ att_src,
                            const float* __restrict__ att_dst) {
    int row = blockIdx.x;
    int tid = threadIdx.x;          // 0..191
    int wid = tid >> 5, lane = tid & 31;
    const __half2* hrow = (const __half2*)(g_hh + (size_t)row * C_);
    float2 hv = __half22float2(hrow[tid]);
    float2 as = *(const float2*)(att_src + 2 * tid);
    float2 ad = *(const float2*)(att_dst + 2 * tid);
    float ps = hv.x * as.x + hv.y * as.y;
    float pd = hv.x * ad.x + hv.y * ad.y;
#pragma unroll
    for (int o = 16; o; o >>= 1) {
        ps += __shfl_down_sync(0xffffffffu, ps, o);
        pd += __shfl_down_sync(0xffffffffu, pd, o);
    }
    if (lane == 0) {
        g_asrc[(size_t)row * H_ + wid] = ps;
        g_adst[(size_t)row * H_ + wid] = pd;
    }
}

// ------- fused GAT gather + residual + LN2 (192 thr, warp = head, half2) -----
// |a| <= ~0.5 for this data scale, so exp(a) without max-shift is exact-safe
// (softmax is shift-invariant; only rounding differs).
__global__ void gather_ln2_kernel(const float* __restrict__ x,
                                  const float* __restrict__ b_gat,
                                  const float* __restrict__ ln2g,
                                  const float* __restrict__ ln2b,
                                  float* __restrict__ x1out,
                                  __half* __restrict__ xnh) {
    int t = blockIdx.x;
    int b = blockIdx.y;
    int tid = threadIdx.x;          // 0..191
    int wid = tid >> 5;             // head
    int start = g_rowptr[t], end = g_rowptr[t + 1];
    const float* asb = g_asrc + (size_t)b * T_ * H_;
    const __half* hb = g_hh + (size_t)b * T_ * C_;

    __shared__ float sadst[H_];
    __shared__ int ssrc[64];
    __shared__ float sw[H_][64];
    if (tid < H_) sadst[tid] = g_adst[((size_t)b * T_ + t) * H_ + tid];

    float2 acc = make_float2(0.f, 0.f);
    float den = 0.f;

    for (int e0 = start; e0 < end; e0 += 64) {
        int n = min(64, end - e0);
        __syncthreads();            // protect previous chunk's smem reads + sadst
        if (tid < n) ssrc[tid] = g_col[e0 + tid];
#pragma unroll
        for (int u = 0; u < 2; u++) {
            int q = tid + u * 192;  // covers 0..383 = 6 heads x 64 edges
            int he = q >> 6, j = q & 63;
            if (j < n) {
                int s = g_col[e0 + j];
                float a = asb[s * H_ + he] + sadst[he];
                a = a >= 0.0f ? a : NEG_SLOPE * a;
                sw[he][j] = __expf(a);
            }
        }
        __syncthreads();
#pragma unroll 4
        for (int j = 0; j < n; j++) {
            float w = sw[wid][j];
            den += w;
            float2 hv = __half22float2(
                ((const __half2*)(hb + (size_t)ssrc[j] * C_))[tid]);
            acc.x = fmaf(w, hv.x, acc.x);
            acc.y = fmaf(w, hv.y, acc.y);
        }
    }

    float inv = 1.0f / den;
    size_t ro = ((size_t)b * T_ + t) * C_;
    int c0 = 2 * tid;
    float2 xv = *(const float2*)(x + ro + c0);
    float2 bg = *(const float2*)(b_gat + c0);
    float v0 = xv.x + acc.x * inv + bg.x;
    float v1 = xv.y + acc.y * inv + bg.y;
    *(float2*)(x1out + ro + c0) = make_float2(v0, v1);

    // fused LN2 over the row (384 values across 192 threads)
    float s = v0 + v1, ss = v0 * v0 + v1 * v1;
    int lane = tid & 31;
#pragma unroll
    for (int o = 16; o; o >>= 1) {
        s += __shfl_down_sync(0xffffffffu, s, o);
        ss += __shfl_down_sync(0xffffffffu, ss, o);
    }
    __shared__ float rs[H_], rss[H_];
    if (lane == 0) { rs[wid] = s; rss[wid] = ss; }
    __syncthreads();
    float ts = rs[0] + rs[1] + rs[2] + rs[3] + rs[4] + rs[5];
    float tss = rss[0] + rss[1] + rss[2] + rss[3] + rss[4] + rss[5];
    float mu = ts * (1.0f / C_);
    float var = tss * (1.0f / C_) - mu * mu;
    float r = rsqrtf(var + LN_EPS);
    float2 gg = *(const float2*)(ln2g + c0);
    float2 bb = *(const float2*)(ln2b + c0);
    ((__half2*)(xnh + ro))[tid] =
        __floats2half2_rn((v0 - mu) * r * gg.x + bb.x,
                          (v1 - mu) * r * gg.y + bb.y);
}

// ================== fp16 mma.sync GEMM ======================================
__device__ __forceinline__ void mma_f16(float* c, const uint32_t* a, const uint32_t* b) {
    asm volatile(
        "mma.sync.aligned.m16n8k16.row.col.f32.f16.f16.f32 "
        "{%0,%1,%2,%3}, {%4,%5,%6,%7}, {%8,%9}, {%0,%1,%2,%3};\n"
        : "+f"(c[0]), "+f"(c[1]), "+f"(c[2]), "+f"(c[3])
        : "r"(a[0]), "r"(a[1]), "r"(a[2]), "r"(a[3]), "r"(b[0]), "r"(b[1]));
}

#define CP16(dst, src) \
    asm volatile("cp.async.cg.shared.global [%0], [%1], 16;\n" :: "r"(dst), "l"(src))
#define CP_COMMIT() asm volatile("cp.async.commit_group;\n")
#define CP_WAIT(N)  asm volatile("cp.async.wait_group %0;\n" :: "n"(N))

__device__ __forceinline__ uint32_t smem_u32(const void* p) {
    uint32_t a;
    asm("{ .reg .u64 t; cvta.to.shared.u64 t, %1; cvt.u32.u64 %0, t; }"
        : "=r"(a) : "l"(p));
    return a;
}

#define HSTRIDE 40

// EPI: 0 plain half out, 1 bias+relu half out, 2 bias+residual float out
template <int EPI>
__global__ __launch_bounds__(256, 2)
void gemm_f16_kernel(const __half* __restrict__ A, const __half* __restrict__ Bt,
                     const float* __restrict__ bias, const float* __restrict__ res,
                     void* __restrict__ Cout, int M, int N, int K) {
    __shared__ __align__(16) __half As[2][128][HSTRIDE];
    __shared__ __align__(16) __half Bs[2][128][HSTRIDE];

    const int tid = threadIdx.x;
    const int bx = blockIdx.x, by = blockIdx.y;
    const int warpId = tid >> 5, lane = tid & 31;
    const int wm = warpId & 1;
    const int wn = warpId >> 1;
    const int gID = lane >> 2, tg = lane & 3;

    const __half* Abase = A + (size_t)(by * 128) * K;
    const __half* Bbase = Bt + (size_t)(bx * 128) * K;

    const int nCh = K >> 5;

#define DO_FILL(c, b) do { \
        const __half* As_ = Abase + (c) * 32; \
        const __half* Bs_ = Bbase + (c) * 32; \
        uint32_t ab = smem_u32(&As[b][0][0]); \
        uint32_t bb = smem_u32(&Bs[b][0][0]); \
        _Pragma("unroll") \
        for (int u = 0; u < 4; u++) { \
            int o = tid + u * 256; \
            int o2 = o & 511; \
            int r_ = o2 >> 2, s_ = o2 & 3; \
            uint32_t doff = (uint32_t)(r_ * (HSTRIDE * 2) + s_ * 16); \
            if (o < 512) CP16(ab + doff, As_ + (size_t)r_ * K + s_ * 8); \
            else         CP16(bb + doff, Bs_ + (size_t)r_ * K + s_ * 8); \
        } \
        CP_COMMIT(); \
    } while (0)

    float acc[4][4][4] = {};

    DO_FILL(0, 0);

    for (int it = 0; it < nCh; it++) {
        const int cur = it & 1;
        if (it + 1 < nCh) {
            DO_FILL(it + 1, (it + 1) & 1);
            CP_WAIT(1);
        } else {
            CP_WAIT(0);
        }
        __syncthreads();

#pragma unroll
        for (int kk = 0; kk < 32; kk += 16) {
            uint32_t afr[4][4], bfr[4][2];
#pragma unroll
            for (int mi = 0; mi < 4; mi++) {
                int m0 = wm * 64 + mi * 16;
                afr[mi][0] = *(const uint32_t*)&As[cur][m0 + gID][kk + 2 * tg];
                afr[mi][1] = *(const uint32_t*)&As[cur][m0 + gID + 8][kk + 2 * tg];
                afr[mi][2] = *(const uint32_t*)&As[cur][m0 + gID][kk + 2 * tg + 8];
                afr[mi][3] = *(const uint32_t*)&As[cur][m0 + gID + 8][kk + 2 * tg + 8];
            }
#pragma unroll
            for (int ni = 0; ni < 4; ni++) {
                int n0 = wn * 32 + ni * 8;
                bfr[ni][0] = *(const uint32_t*)&Bs[cur][n0 + gID][kk + 2 * tg];
                bfr[ni][1] = *(const uint32_t*)&Bs[cur][n0 + gID][kk + 2 * tg + 8];
            }
#pragma unroll
            for (int mi = 0; mi < 4; mi++)
#pragma unroll
                for (int ni = 0; ni < 4; ni++)
                    mma_f16(acc[mi][ni], afr[mi], bfr[ni]);
        }
        __syncthreads();
    }

#pragma unroll
    for (int mi = 0; mi < 4; mi++) {
        int row0 = by * 128 + wm * 64 + mi * 16 + gID;
#pragma unroll
        for (int ni = 0; ni < 4; ni++) {
            int col = bx * 128 + wn * 32 + ni * 8 + 2 * tg;
            float b0 = 0.f, b1 = 0.f;
            if (EPI >= 1) { b0 = bias[col]; b1 = bias[col + 1]; }
            float v0 = acc[mi][ni][0] + b0;
            float v1 = acc[mi][ni][1] + b1;
            float v2 = acc[mi][ni][2] + b0;
            float v3 = acc[mi][ni][3] + b1;
            size_t o0 = (size_t)row0 * N + col;
            size_t o1 = (size_t)(row0 + 8) * N + col;
            if (EPI <= 1) {
                if (EPI == 1) {
                    v0 = fmaxf(v0, 0.f); v1 = fmaxf(v1, 0.f);
                    v2 = fmaxf(v2, 0.f); v3 = fmaxf(v3, 0.f);
                }
                __half* Ch = (__half*)Cout;
                *(__half2*)(Ch + o0) = __floats2half2_rn(v0, v1);
                *(__half2*)(Ch + o1) = __floats2half2_rn(v2, v3);
            } else {
                float* Cf = (float*)Cout;
                v0 += res[o0]; v1 += res[o0 + 1];
                v2 += res[o1]; v3 += res[o1 + 1];
                Cf[o0] = v0; Cf[o0 + 1] = v1;
                Cf[o1] = v2; Cf[o1 + 1] = v3;
            }
        }
    }
#undef DO_FILL
}

// ---------------- launch -----------------------------------------------------
extern "C" void kernel_launch(void* const* d_in, const int* in_sizes, int n_in,
                              void* d_out, int out_size) {
    const float* x      = (const float*)d_in[0];
    const int*   ei     = (const int*)d_in[1];
    const float* W_gat  = (const float*)d_in[2];
    const float* att_s  = (const float*)d_in[3];
    const float* att_d  = (const float*)d_in[4];
    const float* b_gat  = (const float*)d_in[5];
    const float* ln1_g  = (const float*)d_in[6];
    const float* ln1_b  = (const float*)d_in[7];
    const float* ln2_g  = (const float*)d_in[8];
    const float* ln2_b  = (const float*)d_in[9];
    const float* W1     = (const float*)d_in[10];
    const float* b1     = (const float*)d_in[11];
    const float* W2     = (const float*)d_in[12];
    const float* b2     = (const float*)d_in[13];
    float* out = (float*)d_out;

    float *p_x1;
    __half *p_xnh, *p_hh, *p_acth, *p_wgth, *p_w1th, *p_w2th;
    cudaGetSymbolAddress((void**)&p_x1, g_x1);
    cudaGetSymbolAddress((void**)&p_xnh, g_xnh);
    cudaGetSymbolAddress((void**)&p_hh, g_hh);
    cudaGetSymbolAddress((void**)&p_acth, g_acth);
    cudaGetSymbolAddress((void**)&p_wgth, g_wgth);
    cudaGetSymbolAddress((void**)&p_w1th, g_w1th);
    cudaGetSymbolAddress((void**)&p_w2th, g_w2th);

    const int M = B_ * T_;

    {
        dim3 blk(32, 8);
        transpose_h_kernel<<<dim3(C_ / 32, C_ / 32), blk>>>(W_gat, p_wgth, C_, C_);
        transpose_h_kernel<<<dim3(DFF_ / 32, C_ / 32), blk>>>(W1, p_w1th, C_, DFF_);
        transpose_h_kernel<<<dim3(C_ / 32, DFF_ / 32), blk>>>(W2, p_w2th, DFF_, C_);
    }

    csr_count_kernel<<<(E_ + 255) / 256, 256>>>(ei);
    csr_scan_kernel<<<1, 1024>>>();
    csr_scatter_kernel<<<(NEDGE + 255) / 256, 256>>>(ei);

    ln_kernel<<<M, 128>>>(x, ln1_g, ln1_b, p_xnh);

    // h = xn @ W_gat  (half out)
    {
        dim3 grid(C_ / 128, M / 128);
        gemm_f16_kernel<0><<<grid, 256>>>(p_xnh, p_wgth, nullptr, nullptr,
                                          p_hh, M, C_, C_);
    }

    attn_kernel<<<M, 192>>>(att_s, att_d);

    // gather + residual + LN2 fused
    {
        dim3 grid(T_, B_);
        gather_ln2_kernel<<<grid, 192>>>(x, b_gat, ln2_g, ln2_b, p_x1, p_xnh);
    }

    // FFN1: act = relu(xn @ W1 + b1)  (half out)
    {
        dim3 grid(DFF_ / 128, M / 128);
        gemm_f16_kernel<1><<<grid, 256>>>(p_xnh, p_w1th, b1, nullptr,
                                          p_acth, M, DFF_, C_);
    }

    // FFN2: out = x1 + act @ W2 + b2  (float out)
    {
        dim3 grid(C_ / 128, M / 128);
        gemm_f16_kernel<2><<<grid, 256>>>(p_acth, p_w2th, b2, p_x1,
                                          out, M, C_, DFF_);
    }
}

// round 15
// speedup vs baseline: 4.7340x; 1.0432x over previous
#include <cuda_runtime.h>
#include <cuda_fp16.h>
#include <math.h>
#include <stdint.h>

#define B_   8
#define T_   4096
#define C_   384
#define H_   6
#define F_   64
#define E_   131072
#define DFF_ 1536
#define NEDGE (E_ + T_)
#define NEG_SLOPE 0.2f
#define LN_EPS 1e-5f

// ---------------- scratch ----------------------------------------------------
__device__ __half g_xnh[B_ * T_ * C_];     // LN output (half, GEMM A)
__device__ __half g_hh[B_ * T_ * C_];      // GAT features h (half)
__device__ float  g_x1[B_ * T_ * C_];      // residual after GAT
__device__ __half g_acth[B_ * T_ * DFF_];  // FFN activations (half)
__device__ float  g_asrc[B_ * T_ * H_];
__device__ float  g_adst[B_ * T_ * H_];
__device__ int    g_cnt[T_];
__device__ int    g_rowptr[T_ + 1];
__device__ int    g_fill[T_];
__device__ int    g_col[NEDGE];
__device__ __half g_wgth[C_ * C_];         // W_gat^T [N][K] half
__device__ __half g_w1th[DFF_ * C_];       // W1^T
__device__ __half g_w2th[C_ * DFF_];       // W2^T

// ---------------- CSR build --------------------------------------------------
__global__ void csr_count_kernel(const int* __restrict__ ei) {
    int e = blockIdx.x * blockDim.x + threadIdx.x;
    if (e < E_) atomicAdd(&g_cnt[ei[E_ + e]], 1);
}

__global__ void csr_scan_kernel() {
    int tid = threadIdx.x;
    int base = tid * 4;
    int c[4];
    int s = 0;
#pragma unroll
    for (int j = 0; j < 4; j++) { c[j] = g_cnt[base + j] + 1; s += c[j]; } // +1 self loop
    int lane = tid & 31, wid = tid >> 5;
    int v = s;
#pragma unroll
    for (int o = 1; o < 32; o <<= 1) {
        int n = __shfl_up_sync(0xffffffffu, v, o);
        if (lane >= o) v += n;
    }
    __shared__ int ws[32];
    if (lane == 31) ws[wid] = v;
    __syncthreads();
    if (wid == 0) {
        int w = ws[lane];
#pragma unroll
        for (int o = 1; o < 32; o <<= 1) {
            int n = __shfl_up_sync(0xffffffffu, w, o);
            if (lane >= o) w += n;
        }
        ws[lane] = w;
    }
    __syncthreads();
    int excl = v - s + (wid ? ws[wid - 1] : 0);
    int p = excl;
#pragma unroll
    for (int j = 0; j < 4; j++) {
        g_rowptr[base + j] = p;
        g_fill[base + j] = p;
        g_cnt[base + j] = 0;          // reset for next graph replay
        p += c[j];
    }
    if (tid == 1023) g_rowptr[T_] = p;
}

__global__ void csr_scatter_kernel(const int* __restrict__ ei) {
    int e = blockIdx.x * blockDim.x + threadIdx.x;
    if (e < E_) {
        int d = ei[E_ + e];
        int pos = atomicAdd(&g_fill[d], 1);
        g_col[pos] = ei[e];
    } else if (e < NEDGE) {
        int t = e - E_;
        int pos = atomicAdd(&g_fill[t], 1);
        g_col[pos] = t;
    }
}

// ---------------- weight transpose (float in -> half out) --------------------
__global__ void transpose_h_kernel(const float* __restrict__ in,
                                   __half* __restrict__ outp, int R, int Cc) {
    __shared__ float t[32][33];
    int x = blockIdx.x * 32 + threadIdx.x;
    int y = blockIdx.y * 32 + threadIdx.y;
#pragma unroll
    for (int j = 0; j < 32; j += 8)
        t[threadIdx.y + j][threadIdx.x] = in[(size_t)(y + j) * Cc + x];
    __syncthreads();
    x = blockIdx.y * 32 + threadIdx.x;
    y = blockIdx.x * 32 + threadIdx.y;
#pragma unroll
    for (int j = 0; j < 32; j += 8)
        outp[(size_t)(y + j) * R + x] = __float2half_rn(t[threadIdx.x][threadIdx.y + j]);
}

// ---------------- LayerNorm (float in, half out) ------------------------------
__global__ void ln_kernel(const float* __restrict__ x,
                          const float* __restrict__ g,
                          const float* __restrict__ b,
                          __half* __restrict__ out) {
    int row = blockIdx.x;
    const float* xr = x + (size_t)row * C_;
    __half* orow = out + (size_t)row * C_;
    int tid = threadIdx.x;
    float v0 = xr[tid], v1 = xr[tid + 128], v2 = xr[tid + 256];
    float s = v0 + v1 + v2;
    float ss = v0 * v0 + v1 * v1 + v2 * v2;
    int lane = tid & 31, wid = tid >> 5;
#pragma unroll
    for (int o = 16; o; o >>= 1) {
        s += __shfl_down_sync(0xffffffffu, s, o);
        ss += __shfl_down_sync(0xffffffffu, ss, o);
    }
    __shared__ float sm_s[4], sm_ss[4];
    if (lane == 0) { sm_s[wid] = s; sm_ss[wid] = ss; }
    __syncthreads();
    float ts = sm_s[0] + sm_s[1] + sm_s[2] + sm_s[3];
    float tss = sm_ss[0] + sm_ss[1] + sm_ss[2] + sm_ss[3];
    float mu = ts * (1.0f / C_);
    float var = tss * (1.0f / C_) - mu * mu;
    float r = rsqrtf(var + LN_EPS);
    orow[tid]       = __float2half_rn((v0 - mu) * r * g[tid]       + b[tid]);
    orow[tid + 128] = __float2half_rn((v1 - mu) * r * g[tid + 128] + b[tid + 128]);
    orow[tid + 256] = __float2half_rn((v2 - mu) * r * g[tid + 256] + b[tid + 256]);
}

// ---------------- attention coefficients (192 thr, warp = head) --------------
__global__ void attn_kernel(const float* __restrict__ att_src,
                            const float* __restrict__ att_dst) {
    int row = blockIdx.x;
    int tid = threadIdx.x;
    int wid = tid >> 5, lane = tid & 31;
    const __half2* hrow = (const __half2*)(g_hh + (size_t)row * C_);
    float2 hv = __half22float2(hrow[tid]);
    float2 as = *(const float2*)(att_src + 2 * tid);
    float2 ad = *(const float2*)(att_dst + 2 * tid);
    float ps = hv.x * as.x + hv.y * as.y;
    float pd = hv.x * ad.x + hv.y * ad.y;
#pragma unroll
    for (int o = 16; o; o >>= 1) {
        ps += __shfl_down_sync(0xffffffffu, ps, o);
        pd += __shfl_down_sync(0xffffffffu, pd, o);
    }
    if (lane == 0) {
        g_asrc[(size_t)row * H_ + wid] = ps;
        g_adst[(size_t)row * H_ + wid] = pd;
    }
}

// ------- fused GAT gather + residual + LN2 (192 thr, warp = head, half2) -----
__global__ void gather_ln2_kernel(const float* __restrict__ x,
                                  const float* __restrict__ b_gat,
                                  const float* __restrict__ ln2g,
                                  const float* __restrict__ ln2b,
                                  float* __restrict__ x1out,
                                  __half* __restrict__ xnh) {
    int t = blockIdx.x;
    int b = blockIdx.y;
    int tid = threadIdx.x;
    int wid = tid >> 5;             // head
    int start = g_rowptr[t], end = g_rowptr[t + 1];
    const float* asb = g_asrc + (size_t)b * T_ * H_;
    const __half* hb = g_hh + (size_t)b * T_ * C_;

    __shared__ float sadst[H_];
    __shared__ int ssrc[64];
    __shared__ float sw[H_][64];
    if (tid < H_) sadst[tid] = g_adst[((size_t)b * T_ + t) * H_ + tid];

    float2 acc = make_float2(0.f, 0.f);
    float den = 0.f;

    for (int e0 = start; e0 < end; e0 += 64) {
        int n = min(64, end - e0);
        __syncthreads();
        if (tid < n) ssrc[tid] = g_col[e0 + tid];
#pragma unroll
        for (int u = 0; u < 2; u++) {
            int q = tid + u * 192;
            int he = q >> 6, j = q & 63;
            if (j < n) {
                int s = g_col[e0 + j];
                float a = asb[s * H_ + he] + sadst[he];
                a = a >= 0.0f ? a : NEG_SLOPE * a;
                sw[he][j] = __expf(a);
            }
        }
        __syncthreads();
#pragma unroll 4
        for (int j = 0; j < n; j++) {
            float w = sw[wid][j];
            den += w;
            float2 hv = __half22float2(
                ((const __half2*)(hb + (size_t)ssrc[j] * C_))[tid]);
            acc.x = fmaf(w, hv.x, acc.x);
            acc.y = fmaf(w, hv.y, acc.y);
        }
    }

    float inv = 1.0f / den;
    size_t ro = ((size_t)b * T_ + t) * C_;
    int c0 = 2 * tid;
    float2 xv = *(const float2*)(x + ro + c0);
    float2 bg = *(const float2*)(b_gat + c0);
    float v0 = xv.x + acc.x * inv + bg.x;
    float v1 = xv.y + acc.y * inv + bg.y;
    *(float2*)(x1out + ro + c0) = make_float2(v0, v1);

    float s = v0 + v1, ss = v0 * v0 + v1 * v1;
    int lane = tid & 31;
#pragma unroll
    for (int o = 16; o; o >>= 1) {
        s += __shfl_down_sync(0xffffffffu, s, o);
        ss += __shfl_down_sync(0xffffffffu, ss, o);
    }
    __shared__ float rs[H_], rss[H_];
    if (lane == 0) { rs[wid] = s; rss[wid] = ss; }
    __syncthreads();
    float ts = rs[0] + rs[1] + rs[2] + rs[3] + rs[4] + rs[5];
    float tss = rss[0] + rss[1] + rss[2] + rss[3] + rss[4] + rss[5];
    float mu = ts * (1.0f / C_);
    float var = tss * (1.0f / C_) - mu * mu;
    float r = rsqrtf(var + LN_EPS);
    float2 gg = *(const float2*)(ln2g + c0);
    float2 bb = *(const float2*)(ln2b + c0);
    ((__half2*)(xnh + ro))[tid] =
        __floats2half2_rn((v0 - mu) * r * gg.x + bb.x,
                          (v1 - mu) * r * gg.y + bb.y);
}

// ================== fp16 mma.sync GEMM (ldmatrix fragment loads) =============
__device__ __forceinline__ void mma_f16(float* c, const uint32_t* a, const uint32_t* b) {
    asm volatile(
        "mma.sync.aligned.m16n8k16.row.col.f32.f16.f16.f32 "
        "{%0,%1,%2,%3}, {%4,%5,%6,%7}, {%8,%9}, {%0,%1,%2,%3};\n"
        : "+f"(c[0]), "+f"(c[1]), "+f"(c[2]), "+f"(c[3])
        : "r"(a[0]), "r"(a[1]), "r"(a[2]), "r"(a[3]), "r"(b[0]), "r"(b[1]));
}

#define LDSM4(r0, r1, r2, r3, addr) \
    asm volatile("ldmatrix.sync.aligned.m8n8.x4.shared.b16 {%0,%1,%2,%3}, [%4];" \
                 : "=r"(r0), "=r"(r1), "=r"(r2), "=r"(r3) : "r"(addr))

#define CP16(dst, src) \
    asm volatile("cp.async.cg.shared.global [%0], [%1], 16;\n" :: "r"(dst), "l"(src))
#define CP_COMMIT() asm volatile("cp.async.commit_group;\n")
#define CP_WAIT(N)  asm volatile("cp.async.wait_group %0;\n" :: "n"(N))

__device__ __forceinline__ uint32_t smem_u32(const void* p) {
    uint32_t a;
    asm("{ .reg .u64 t; cvta.to.shared.u64 t, %1; cvt.u32.u64 %0, t; }"
        : "=r"(a) : "l"(p));
    return a;
}

#define HSTRIDE 40   // halves per row; ldmatrix 8-row phases hit 32 distinct banks

// EPI: 0 plain half out, 1 bias+relu half out, 2 bias+residual float out
template <int EPI>
__global__ __launch_bounds__(256, 2)
void gemm_f16_kernel(const __half* __restrict__ A, const __half* __restrict__ Bt,
                     const float* __restrict__ bias, const float* __restrict__ res,
                     void* __restrict__ Cout, int M, int N, int K) {
    __shared__ __align__(16) __half As[2][128][HSTRIDE];
    __shared__ __align__(16) __half Bs[2][128][HSTRIDE];

    const int tid = threadIdx.x;
    const int bx = blockIdx.x, by = blockIdx.y;
    const int warpId = tid >> 5, lane = tid & 31;
    const int wm = warpId & 1;
    const int wn = warpId >> 1;
    const int gID = lane >> 2, tg = lane & 3;

    const __half* Abase = A + (size_t)(by * 128) * K;
    const __half* Bbase = Bt + (size_t)(bx * 128) * K;

    const int nCh = K >> 5;

    // ldmatrix lane->address offsets (halves)
    const uint32_t aoff = (uint32_t)((wm * 64 + (lane & 15)) * HSTRIDE +
                                     (lane >> 4) * 8) * 2;
    const uint32_t boff = (uint32_t)((wn * 32 + (lane & 7) + (lane >> 4) * 8) * HSTRIDE +
                                     ((lane >> 3) & 1) * 8) * 2;
    const uint32_t aB0 = smem_u32(&As[0][0][0]) + aoff;
    const uint32_t aB1 = smem_u32(&As[1][0][0]) + aoff;
    const uint32_t bB0 = smem_u32(&Bs[0][0][0]) + boff;
    const uint32_t bB1 = smem_u32(&Bs[1][0][0]) + boff;

#define DO_FILL(c, b) do { \
        const __half* As_ = Abase + (c) * 32; \
        const __half* Bs_ = Bbase + (c) * 32; \
        uint32_t ab = smem_u32(&As[b][0][0]); \
        uint32_t bb = smem_u32(&Bs[b][0][0]); \
        _Pragma("unroll") \
        for (int u = 0; u < 4; u++) { \
            int o = tid + u * 256; \
            int o2 = o & 511; \
            int r_ = o2 >> 2, s_ = o2 & 3; \
            uint32_t doff = (uint32_t)(r_ * (HSTRIDE * 2) + s_ * 16); \
            if (o < 512) CP16(ab + doff, As_ + (size_t)r_ * K + s_ * 8); \
            else         CP16(bb + doff, Bs_ + (size_t)r_ * K + s_ * 8); \
        } \
        CP_COMMIT(); \
    } while (0)

    float acc[4][4][4] = {};

    DO_FILL(0, 0);

    for (int it = 0; it < nCh; it++) {
        const int cur = it & 1;
        if (it + 1 < nCh) {
            DO_FILL(it + 1, (it + 1) & 1);
            CP_WAIT(1);
        } else {
            CP_WAIT(0);
        }
        __syncthreads();

        const uint32_t aB = cur ? aB1 : aB0;
        const uint32_t bB = cur ? bB1 : bB0;
#pragma unroll
        for (int kk = 0; kk < 32; kk += 16) {
            uint32_t afr[4][4], bfr[4][2];
#pragma unroll
            for (int mi = 0; mi < 4; mi++) {
                LDSM4(afr[mi][0], afr[mi][1], afr[mi][2], afr[mi][3],
                      aB + (uint32_t)(mi * 16 * HSTRIDE + kk) * 2);
            }
#pragma unroll
            for (int ng = 0; ng < 2; ng++) {
                LDSM4(bfr[2 * ng][0], bfr[2 * ng][1], bfr[2 * ng + 1][0], bfr[2 * ng + 1][1],
                      bB + (uint32_t)(ng * 16 * HSTRIDE + kk) * 2);
            }
#pragma unroll
            for (int mi = 0; mi < 4; mi++)
#pragma unroll
                for (int ni = 0; ni < 4; ni++)
                    mma_f16(acc[mi][ni], afr[mi], bfr[ni]);
        }
        __syncthreads();
    }

#pragma unroll
    for (int mi = 0; mi < 4; mi++) {
        int row0 = by * 128 + wm * 64 + mi * 16 + gID;
#pragma unroll
        for (int ni = 0; ni < 4; ni++) {
            int col = bx * 128 + wn * 32 + ni * 8 + 2 * tg;
            float b0 = 0.f, b1 = 0.f;
            if (EPI >= 1) { b0 = bias[col]; b1 = bias[col + 1]; }
            float v0 = acc[mi][ni][0] + b0;
            float v1 = acc[mi][ni][1] + b1;
            float v2 = acc[mi][ni][2] + b0;
            float v3 = acc[mi][ni][3] + b1;
            size_t o0 = (size_t)row0 * N + col;
            size_t o1 = (size_t)(row0 + 8) * N + col;
            if (EPI <= 1) {
                if (EPI == 1) {
                    v0 = fmaxf(v0, 0.f); v1 = fmaxf(v1, 0.f);
                    v2 = fmaxf(v2, 0.f); v3 = fmaxf(v3, 0.f);
                }
                __half* Ch = (__half*)Cout;
                *(__half2*)(Ch + o0) = __floats2half2_rn(v0, v1);
                *(__half2*)(Ch + o1) = __floats2half2_rn(v2, v3);
            } else {
                float* Cf = (float*)Cout;
                v0 += res[o0]; v1 += res[o0 + 1];
                v2 += res[o1]; v3 += res[o1 + 1];
                Cf[o0] = v0; Cf[o0 + 1] = v1;
                Cf[o1] = v2; Cf[o1 + 1] = v3;
            }
        }
    }
#undef DO_FILL
}

// ---------------- launch -----------------------------------------------------
extern "C" void kernel_launch(void* const* d_in, const int* in_sizes, int n_in,
                              void* d_out, int out_size) {
    const float* x      = (const float*)d_in[0];
    const int*   ei     = (const int*)d_in[1];
    const float* W_gat  = (const float*)d_in[2];
    const float* att_s  = (const float*)d_in[3];
    const float* att_d  = (const float*)d_in[4];
    const float* b_gat  = (const float*)d_in[5];
    const float* ln1_g  = (const float*)d_in[6];
    const float* ln1_b  = (const float*)d_in[7];
    const float* ln2_g  = (const float*)d_in[8];
    const float* ln2_b  = (const float*)d_in[9];
    const float* W1     = (const float*)d_in[10];
    const float* b1     = (const float*)d_in[11];
    const float* W2     = (const float*)d_in[12];
    const float* b2     = (const float*)d_in[13];
    float* out = (float*)d_out;

    float *p_x1;
    __half *p_xnh, *p_hh, *p_acth, *p_wgth, *p_w1th, *p_w2th;
    cudaGetSymbolAddress((void**)&p_x1, g_x1);
    cudaGetSymbolAddress((void**)&p_xnh, g_xnh);
    cudaGetSymbolAddress((void**)&p_hh, g_hh);
    cudaGetSymbolAddress((void**)&p_acth, g_acth);
    cudaGetSymbolAddress((void**)&p_wgth, g_wgth);
    cudaGetSymbolAddress((void**)&p_w1th, g_w1th);
    cudaGetSymbolAddress((void**)&p_w2th, g_w2th);

    const int M = B_ * T_;

    {
        dim3 blk(32, 8);
        transpose_h_kernel<<<dim3(C_ / 32, C_ / 32), blk>>>(W_gat, p_wgth, C_, C_);
        transpose_h_kernel<<<dim3(DFF_ / 32, C_ / 32), blk>>>(W1, p_w1th, C_, DFF_);
        transpose_h_kernel<<<dim3(C_ / 32, DFF_ / 32), blk>>>(W2, p_w2th, DFF_, C_);
    }

    csr_count_kernel<<<(E_ + 255) / 256, 256>>>(ei);
    csr_scan_kernel<<<1, 1024>>>();
    csr_scatter_kernel<<<(NEDGE + 255) / 256, 256>>>(ei);

    ln_kernel<<<M, 128>>>(x, ln1_g, ln1_b, p_xnh);

    // h = xn @ W_gat  (half out)
    {
        dim3 grid(C_ / 128, M / 128);
        gemm_f16_kernel<0><<<grid, 256>>>(p_xnh, p_wgth, nullptr, nullptr,
                                          p_hh, M, C_, C_);
    }

    attn_kernel<<<M, 192>>>(att_s, att_d);

    {
        dim3 grid(T_, B_);
        gather_ln2_kernel<<<grid, 192>>>(x, b_gat, ln2_g, ln2_b, p_x1, p_xnh);
    }

    // FFN1: act = relu(xn @ W1 + b1)  (half out)
    {
        dim3 grid(DFF_ / 128, M / 128);
        gemm_f16_kernel<1><<<grid, 256>>>(p_xnh, p_w1th, b1, nullptr,
                                          p_acth, M, DFF_, C_);
    }

    // FFN2: out = x1 + act @ W2 + b2  (float out)
    {
        dim3 grid(C_ / 128, M / 128);
        gemm_f16_kernel<2><<<grid, 256>>>(p_acth, p_w2th, b2, p_x1,
                                          out, M, C_, DFF_);
    }
}